// round 11
// baseline (speedup 1.0000x reference)
#include <cuda_runtime.h>
#include <cuda_fp16.h>
#include <cstdint>
#include <math.h>

// ---------------------------------------------------------------------------
// Problem constants
// ---------------------------------------------------------------------------
#define E_DIM   1024
#define HID_DIM 4096
#define WSZ     64
#define M_TOK   16384

// ---------------------------------------------------------------------------
// Scratch (__device__ globals; no allocation allowed)
// ---------------------------------------------------------------------------
__device__ float  g_AT [M_TOK * E_DIM];
__device__ float  g_X1 [M_TOK * E_DIM];
__device__ float  g_F  [M_TOK * E_DIM];
__device__ __half g_Qh [M_TOK * E_DIM];
__device__ __half g_Kh [M_TOK * E_DIM];
__device__ __half g_Vh [M_TOK * E_DIM];
__device__ __half g_xh [M_TOK * E_DIM];
__device__ __half g_X1h[M_TOK * E_DIM];
__device__ __half g_Hh [(size_t)M_TOK * HID_DIM];
__device__ __half g_Wqh[E_DIM * E_DIM];
__device__ __half g_Wkh[E_DIM * E_DIM];
__device__ __half g_Wvh[E_DIM * E_DIM];
__device__ __half g_W1h[(size_t)E_DIM * HID_DIM];
__device__ __half g_W2h[(size_t)E_DIM * HID_DIM];

// ---------------------------------------------------------------------------
// PTX helpers
// ---------------------------------------------------------------------------
__device__ __forceinline__ uint32_t smem_to_u32(const void* p) {
    uint32_t a;
    asm("{ .reg .u64 t; cvta.to.shared.u64 t, %1; cvt.u32.u64 %0, t; }"
        : "=r"(a) : "l"(p));
    return a;
}

#define CP_ASYNC16(saddr, gptr) \
    asm volatile("cp.async.cg.shared.global [%0], [%1], 16;" \
                 :: "r"(saddr), "l"(gptr))
#define CP_COMMIT() asm volatile("cp.async.commit_group;" ::: "memory")
#define CP_WAIT(n)  asm volatile("cp.async.wait_group %0;" :: "n"(n) : "memory")

#define LDMATRIX_X4(r0, r1, r2, r3, addr) \
    asm volatile("ldmatrix.sync.aligned.m8n8.x4.shared.b16 {%0,%1,%2,%3}, [%4];" \
                 : "=r"(r0), "=r"(r1), "=r"(r2), "=r"(r3) : "r"(addr))

#define LDMATRIX_X4_TRANS(r0, r1, r2, r3, addr) \
    asm volatile("ldmatrix.sync.aligned.m8n8.x4.trans.shared.b16 {%0,%1,%2,%3}, [%4];" \
                 : "=r"(r0), "=r"(r1), "=r"(r2), "=r"(r3) : "r"(addr))

__device__ __forceinline__ void mma_fp16(float* c, const uint32_t* a, const uint32_t* b) {
    asm volatile(
        "mma.sync.aligned.m16n8k16.row.col.f32.f16.f16.f32 "
        "{%0,%1,%2,%3}, {%4,%5,%6,%7}, {%8,%9}, {%0,%1,%2,%3};"
        : "+f"(c[0]), "+f"(c[1]), "+f"(c[2]), "+f"(c[3])
        : "r"(a[0]), "r"(a[1]), "r"(a[2]), "r"(a[3]), "r"(b[0]), "r"(b[1]));
}

// ---------------------------------------------------------------------------
// Batched f32 -> f16 conversion: 6 segments in one launch
// ---------------------------------------------------------------------------
struct ConvSegs {
    const float* src[6];
    __half*      dst[6];
    unsigned     end[6];    // exclusive cumulative quad counts
};

__global__ __launch_bounds__(256)
void to_half_batched(ConvSegs cs, unsigned total4)
{
    const unsigned q = blockIdx.x * 256 + threadIdx.x;
    if (q >= total4) return;
    int seg = 0;
#pragma unroll
    for (int i = 0; i < 5; i++) seg += (q >= cs.end[i]) ? 1 : 0;
    const unsigned i = q - (seg ? cs.end[seg - 1] : 0u);
    const float4 v = ((const float4*)cs.src[seg])[i];
    __half2 h0 = __floats2half2_rn(v.x, v.y);
    __half2 h1 = __floats2half2_rn(v.z, v.w);
    uint2 pk;
    pk.x = *(uint32_t*)&h0;
    pk.y = *(uint32_t*)&h1;
    ((uint2*)cs.dst[seg])[i] = pk;
}

// ---------------------------------------------------------------------------
// fp16 tensor-core GEMM (unchanged from R10 winner):
// 128x128x64 block tile, 256 threads (4x2 warps, 32x64 warp tile),
// 3-stage cp.async pipeline (BK=64), one barrier per iteration, 2 CTAs/SM.
// ---------------------------------------------------------------------------
#define A_STRIDE_H 72
#define B_STRIDE_H 136
#define A_TILE_BYTES (128 * A_STRIDE_H * 2)   // 18432
#define B_TILE_BYTES (64 * B_STRIDE_H * 2)    // 17408
#define STAGE_BYTES  (A_TILE_BYTES + B_TILE_BYTES)   // 35840
#define GEMM_SMEM_BYTES (3 * STAGE_BYTES)            // 107520

struct GemmOuts {
    const __half* B[3];
    const float*  bias[3];
    void*         C[3];
};

template<int RELU, int OUT_HALF>
__global__ __launch_bounds__(256, 2)
void gemm_fp16(const __half* __restrict__ A, GemmOuts io,
               int M, int N, int K)
{
    extern __shared__ char smem[];
    const uint32_t sbase = smem_to_u32(smem);

    const int tid = threadIdx.x;
    const int wid = tid >> 5;
    const int lane = tid & 31;
    const int g = lane >> 2;
    const int t = lane & 3;

    const int wm = wid & 3;
    const int wn = wid >> 2;

    const int m0 = blockIdx.y * 128;
    const int n0 = blockIdx.x * 128;
    const int z  = blockIdx.z;

    const __half* Bmat = io.B[z];
    const float*  bias = io.bias[z];

    const __half* Ag = A + (size_t)m0 * K;
    const __half* Bg = Bmat + n0;

    auto load_tile = [&](int k0, int stage) {
        const uint32_t aoff = sbase + (uint32_t)stage * STAGE_BYTES;
        const uint32_t boff = aoff + A_TILE_BYTES;
#pragma unroll
        for (int i = 0; i < 4; i++) {
            const int s = tid + i * 256;
            const int r = s >> 3, c8 = (s & 7) << 3;
            CP_ASYNC16(aoff + (uint32_t)(r * A_STRIDE_H + c8) * 2,
                       Ag + (size_t)r * K + k0 + c8);
        }
#pragma unroll
        for (int i = 0; i < 4; i++) {
            const int s = tid + i * 256;
            const int r = s >> 4, c8 = (s & 15) << 3;
            CP_ASYNC16(boff + (uint32_t)(r * B_STRIDE_H + c8) * 2,
                       Bg + (size_t)(k0 + r) * N + c8);
        }
        CP_COMMIT();
    };

    float acc[2][8][4];
#pragma unroll
    for (int mi = 0; mi < 2; mi++)
#pragma unroll
        for (int ni = 0; ni < 8; ni++)
#pragma unroll
            for (int j = 0; j < 4; j++) acc[mi][ni][j] = 0.f;

    const int NK = K >> 6;
    load_tile(0, 0);
    load_tile(64, 1);

    const int a_row = wm * 32 + (lane & 7) + ((lane >> 3) & 1) * 8;
    const int a_col = (lane >> 4) << 3;
    const int b_row = (lane & 7) + ((lane >> 3) & 1) * 8;
    const int b_col = wn * 64 + ((lane >> 4) << 3);

    for (int kt = 0; kt < NK; kt++) {
        CP_WAIT(1);
        __syncthreads();

        if (kt + 2 < NK) load_tile((kt + 2) << 6, (kt + 2) % 3);
        else CP_COMMIT();

        const uint32_t sA = sbase + (uint32_t)(kt % 3) * STAGE_BYTES;
        const uint32_t sB = sA + A_TILE_BYTES;

#pragma unroll
        for (int kk = 0; kk < 4; kk++) {
            uint32_t a[2][4];
#pragma unroll
            for (int mi = 0; mi < 2; mi++) {
                const uint32_t addr = sA +
                    (uint32_t)((a_row + mi * 16) * A_STRIDE_H + a_col + kk * 16) * 2;
                LDMATRIX_X4(a[mi][0], a[mi][1], a[mi][2], a[mi][3], addr);
            }
            uint32_t b[4][4];
#pragma unroll
            for (int ni4 = 0; ni4 < 4; ni4++) {
                const uint32_t addr = sB +
                    (uint32_t)((b_row + kk * 16) * B_STRIDE_H + b_col + ni4 * 16) * 2;
                LDMATRIX_X4_TRANS(b[ni4][0], b[ni4][1], b[ni4][2], b[ni4][3], addr);
            }
#pragma unroll
            for (int mi = 0; mi < 2; mi++)
#pragma unroll
                for (int ni = 0; ni < 8; ni++)
                    mma_fp16(acc[mi][ni], a[mi], &b[ni >> 1][(ni & 1) * 2]);
        }
    }

#pragma unroll
    for (int mi = 0; mi < 2; mi++) {
        const int row = m0 + wm * 32 + mi * 16 + g;
#pragma unroll
        for (int ni = 0; ni < 8; ni++) {
            const int col = n0 + wn * 64 + ni * 8 + t * 2;
            const float b0 = bias[col], b1 = bias[col + 1];
            float2 lo = make_float2(acc[mi][ni][0] + b0, acc[mi][ni][1] + b1);
            float2 hi = make_float2(acc[mi][ni][2] + b0, acc[mi][ni][3] + b1);
            if (RELU) {
                lo.x = fmaxf(lo.x, 0.f); lo.y = fmaxf(lo.y, 0.f);
                hi.x = fmaxf(hi.x, 0.f); hi.y = fmaxf(hi.y, 0.f);
            }
            if (OUT_HALF) {
                __half* Ch = (__half*)io.C[z];
                __half2 l2 = __floats2half2_rn(lo.x, lo.y);
                __half2 h2 = __floats2half2_rn(hi.x, hi.y);
                *(__half2*)(Ch + (size_t)row * N + col) = l2;
                *(__half2*)(Ch + (size_t)(row + 8) * N + col) = h2;
            } else {
                float* Cf = (float*)io.C[z];
                *(float2*)(Cf + (size_t)row * N + col) = lo;
                *(float2*)(Cf + (size_t)(row + 8) * N + col) = hi;
            }
        }
    }
}

// ---------------------------------------------------------------------------
// Tensor-core window attention: one block per 64-token window, 8 warps.
// Phase 1: S = Q K^T streamed in 128-wide K chunks (8 iterations).
// Phase 2: softmax (fp32) -> P fp16 -> O = P V in 128-wide E chunks.
// ---------------------------------------------------------------------------
#define AT_S_STRIDE 68    // floats
#define AT_P_STRIDE 72    // halves
#define AT_QK_STRIDE 136  // halves (128 + 8 pad)
#define AT_V_STRIDE 136   // halves
#define AT_P_OFF (64 * AT_S_STRIDE * 4)                 // 17408
#define AT_U_OFF (AT_P_OFF + 64 * AT_P_STRIDE * 2)      // 26624
#define AT_Q_BYTES (64 * AT_QK_STRIDE * 2)              // 17408
#define AT_QK_STAGE (2 * AT_Q_BYTES)                    // 34816
#define AT_V_STAGE (64 * AT_V_STRIDE * 2)               // 17408
#define AT_SMEM (AT_U_OFF + 2 * AT_QK_STAGE)            // 96256

__global__ __launch_bounds__(256, 2)
void window_attn_mma(const __half* __restrict__ Qh, const __half* __restrict__ Kh,
                     const __half* __restrict__ Vh, float* __restrict__ O)
{
    extern __shared__ char smem[];
    const uint32_t sbase = smem_to_u32(smem);
    float* Sf = (float*)smem;

    const int tid = threadIdx.x;
    const int wid = tid >> 5;
    const int lane = tid & 31;
    const int g = lane >> 2, t = lane & 3;
    const int wm = wid & 3;
    const int wn = wid >> 2;

    const int w = blockIdx.x;
    const __half* Qw = Qh + (size_t)w * WSZ * E_DIM;
    const __half* Kw = Kh + (size_t)w * WSZ * E_DIM;
    const __half* Vw = Vh + (size_t)w * WSZ * E_DIM;
    float* Ow = O + (size_t)w * WSZ * E_DIM;

    const int lrow  = (lane & 7) + ((lane >> 3) & 1) * 8;
    const int lcol8 = (lane >> 4) << 3;

    // ---- Phase 1: S = Q K^T, 128-wide K chunks ----
    auto load_qk = [&](int kc, int st) {
        const uint32_t qoff = sbase + AT_U_OFF + (uint32_t)st * AT_QK_STAGE;
        const uint32_t koff = qoff + AT_Q_BYTES;
#pragma unroll
        for (int i = 0; i < 4; i++) {
            const int s = tid + i * 256;        // 0..1023
            const int r = s >> 4, c8 = (s & 15) << 3;
            CP_ASYNC16(qoff + (uint32_t)(r * AT_QK_STRIDE + c8) * 2,
                       Qw + (size_t)r * E_DIM + kc * 128 + c8);
            CP_ASYNC16(koff + (uint32_t)(r * AT_QK_STRIDE + c8) * 2,
                       Kw + (size_t)r * E_DIM + kc * 128 + c8);
        }
        CP_COMMIT();
    };

    float accS[4][4];
#pragma unroll
    for (int nt = 0; nt < 4; nt++)
#pragma unroll
        for (int j = 0; j < 4; j++) accS[nt][j] = 0.f;

    load_qk(0, 0);
    for (int kc = 0; kc < 8; kc++) {
        if (kc < 7) { load_qk(kc + 1, (kc + 1) & 1); CP_WAIT(1); }
        else        { CP_WAIT(0); }
        __syncthreads();

        const uint32_t qs = sbase + AT_U_OFF + (uint32_t)(kc & 1) * AT_QK_STAGE;
        const uint32_t ks = qs + AT_Q_BYTES;

#pragma unroll
        for (int kt = 0; kt < 8; kt++) {
            uint32_t a[4];
            LDMATRIX_X4(a[0], a[1], a[2], a[3],
                qs + (uint32_t)((wm * 16 + lrow) * AT_QK_STRIDE + lcol8 + kt * 16) * 2);
            uint32_t b[2][4];
#pragma unroll
            for (int h = 0; h < 2; h++)
                LDMATRIX_X4(b[h][0], b[h][1], b[h][2], b[h][3],
                    ks + (uint32_t)((wn * 32 + h * 16 + lrow) * AT_QK_STRIDE + lcol8 + kt * 16) * 2);
#pragma unroll
            for (int nt = 0; nt < 4; nt++) {
                uint32_t bf[2] = { b[nt >> 1][nt & 1], b[nt >> 1][(nt & 1) + 2] };
                mma_fp16(accS[nt], a, bf);
            }
        }
        __syncthreads();
    }

    // scale & write S (fp32)
    const float SCALE = 0.03125f;  // 1024^-0.5
#pragma unroll
    for (int nt = 0; nt < 4; nt++) {
        const int row = wm * 16 + g;
        const int col = wn * 32 + nt * 8 + t * 2;
        Sf[row * AT_S_STRIDE + col]           = accS[nt][0] * SCALE;
        Sf[row * AT_S_STRIDE + col + 1]       = accS[nt][1] * SCALE;
        Sf[(row + 8) * AT_S_STRIDE + col]     = accS[nt][2] * SCALE;
        Sf[(row + 8) * AT_S_STRIDE + col + 1] = accS[nt][3] * SCALE;
    }
    __syncthreads();

    // ---- softmax (4 threads per row) -> P fp16 ----
    {
        const int row = tid >> 2;
        const int part = (tid & 3) << 4;
        float vb[16];
        float m = -1e30f;
#pragma unroll
        for (int j = 0; j < 16; j++) {
            vb[j] = Sf[row * AT_S_STRIDE + part + j];
            m = fmaxf(m, vb[j]);
        }
        m = fmaxf(m, __shfl_xor_sync(0xffffffffu, m, 1));
        m = fmaxf(m, __shfl_xor_sync(0xffffffffu, m, 2));
        float s = 0.f;
#pragma unroll
        for (int j = 0; j < 16; j++) { vb[j] = __expf(vb[j] - m); s += vb[j]; }
        s += __shfl_xor_sync(0xffffffffu, s, 1);
        s += __shfl_xor_sync(0xffffffffu, s, 2);
        const float inv = 1.f / s;
        __half* Ph = (__half*)(smem + AT_P_OFF);
#pragma unroll
        for (int j = 0; j < 16; j++)
            Ph[row * AT_P_STRIDE + part + j] = __float2half(vb[j] * inv);
    }
    __syncthreads();

    // ---- Phase 2: O = P V ----
    uint32_t pf[4][4];
#pragma unroll
    for (int kt = 0; kt < 4; kt++)
        LDMATRIX_X4(pf[kt][0], pf[kt][1], pf[kt][2], pf[kt][3],
            sbase + AT_P_OFF +
            (uint32_t)((wm * 16 + lrow) * AT_P_STRIDE + lcol8 + kt * 16) * 2);

    auto load_v = [&](int ec, int st) {
        const uint32_t voff = sbase + AT_U_OFF + (uint32_t)st * AT_V_STAGE;
#pragma unroll
        for (int i = 0; i < 4; i++) {
            const int s = tid + i * 256;
            const int r = s >> 4, c8 = (s & 15) << 3;
            CP_ASYNC16(voff + (uint32_t)(r * AT_V_STRIDE + c8) * 2,
                       Vw + (size_t)r * E_DIM + ec * 128 + c8);
        }
        CP_COMMIT();
    };

    load_v(0, 0);
    for (int ec = 0; ec < 8; ec++) {
        if (ec < 7) { load_v(ec + 1, (ec + 1) & 1); CP_WAIT(1); }
        else        { CP_WAIT(0); }
        __syncthreads();

        const uint32_t vs = sbase + AT_U_OFF + (uint32_t)(ec & 1) * AT_V_STAGE;
        float acc[8][4];
#pragma unroll
        for (int ni = 0; ni < 8; ni++)
#pragma unroll
            for (int j = 0; j < 4; j++) acc[ni][j] = 0.f;

#pragma unroll
        for (int kt = 0; kt < 4; kt++) {
#pragma unroll
            for (int nt4 = 0; nt4 < 4; nt4++) {
                uint32_t b[4];
                LDMATRIX_X4_TRANS(b[0], b[1], b[2], b[3],
                    vs + (uint32_t)((lrow + kt * 16) * AT_V_STRIDE +
                                    wn * 64 + lcol8 + nt4 * 16) * 2);
                mma_fp16(acc[2 * nt4],     pf[kt], &b[0]);
                mma_fp16(acc[2 * nt4 + 1], pf[kt], &b[2]);
            }
        }

#pragma unroll
        for (int ni = 0; ni < 8; ni++) {
            const int row = wm * 16 + g;
            const int col = ec * 128 + wn * 64 + ni * 8 + t * 2;
            *(float2*)(Ow + (size_t)row * E_DIM + col) =
                make_float2(acc[ni][0], acc[ni][1]);
            *(float2*)(Ow + (size_t)(row + 8) * E_DIM + col) =
                make_float2(acc[ni][2], acc[ni][3]);
        }
        __syncthreads();
    }
}

// ---------------------------------------------------------------------------
// out = LayerNorm(A + B) * g + be; optionally also out_h = f16(out)
// Warp-per-row: 8 rows per 256-thread block, shfl-only reduction.
// ---------------------------------------------------------------------------
template<int DUAL>
__global__ __launch_bounds__(256)
void add_ln(const float* __restrict__ A, const float* __restrict__ B,
            const float* __restrict__ g, const float* __restrict__ be,
            float* __restrict__ out, __half* __restrict__ out_h)
{
    const int warp = threadIdx.x >> 5;
    const int lane = threadIdx.x & 31;
    const int row = blockIdx.x * 8 + warp;

    const float* Ar = A + (size_t)row * E_DIM;
    const float* Br = B + (size_t)row * E_DIM;

    float4 vv[8];
    float s = 0.f, sq = 0.f;
#pragma unroll
    for (int k = 0; k < 8; k++) {
        const int col = k * 128 + lane * 4;
        const float4 a = *(const float4*)(Ar + col);
        const float4 b = *(const float4*)(Br + col);
        float4 v;
        v.x = a.x + b.x; v.y = a.y + b.y; v.z = a.z + b.z; v.w = a.w + b.w;
        vv[k] = v;
        s  += v.x + v.y + v.z + v.w;
        sq += v.x * v.x + v.y * v.y + v.z * v.z + v.w * v.w;
    }
#pragma unroll
    for (int o = 16; o > 0; o >>= 1) {
        s  += __shfl_xor_sync(0xffffffffu, s, o);
        sq += __shfl_xor_sync(0xffffffffu, sq, o);
    }
    const float mean = s * (1.f / E_DIM);
    const float var  = sq * (1.f / E_DIM) - mean * mean;
    const float rstd = rsqrtf(var + 1e-5f);

#pragma unroll
    for (int k = 0; k < 8; k++) {
        const int col = k * 128 + lane * 4;
        const float4 gg = *(const float4*)(g + col);
        const float4 bb = *(const float4*)(be + col);
        float4 o4;
        o4.x = (vv[k].x - mean) * rstd * gg.x + bb.x;
        o4.y = (vv[k].y - mean) * rstd * gg.y + bb.y;
        o4.z = (vv[k].z - mean) * rstd * gg.z + bb.z;
        o4.w = (vv[k].w - mean) * rstd * gg.w + bb.w;
        *(float4*)(out + (size_t)row * E_DIM + col) = o4;
        if (DUAL) {
            __half2 h0 = __floats2half2_rn(o4.x, o4.y);
            __half2 h1 = __floats2half2_rn(o4.z, o4.w);
            uint2 pk;
            pk.x = *(uint32_t*)&h0;
            pk.y = *(uint32_t*)&h1;
            *(uint2*)(out_h + (size_t)row * E_DIM + col) = pk;
        }
    }
}

// ---------------------------------------------------------------------------
extern "C" void kernel_launch(void* const* d_in, const int* in_sizes, int n_in,
                              void* d_out, int out_size)
{
    const float* x   = (const float*)d_in[0];
    const float* Wq  = (const float*)d_in[1];
    const float* bq  = (const float*)d_in[2];
    const float* Wk  = (const float*)d_in[3];
    const float* bk  = (const float*)d_in[4];
    const float* Wv  = (const float*)d_in[5];
    const float* bv  = (const float*)d_in[6];
    const float* g1  = (const float*)d_in[7];
    const float* be1 = (const float*)d_in[8];
    const float* W1  = (const float*)d_in[9];
    const float* b1  = (const float*)d_in[10];
    const float* W2  = (const float*)d_in[11];
    const float* b2  = (const float*)d_in[12];
    const float* g2  = (const float*)d_in[13];
    const float* be2 = (const float*)d_in[14];
    float* out = (float*)d_out;

    const int M = in_sizes[0] / E_DIM;   // 16384

    float *Ap, *X1p, *Fp;
    __half *Qh, *Kh, *Vh, *xh, *X1h, *Hh, *Wqh, *Wkh, *Wvh, *W1h, *W2h;
    cudaGetSymbolAddress((void**)&Ap,  g_AT);
    cudaGetSymbolAddress((void**)&X1p, g_X1);
    cudaGetSymbolAddress((void**)&Fp,  g_F);
    cudaGetSymbolAddress((void**)&Qh,  g_Qh);
    cudaGetSymbolAddress((void**)&Kh,  g_Kh);
    cudaGetSymbolAddress((void**)&Vh,  g_Vh);
    cudaGetSymbolAddress((void**)&xh,  g_xh);
    cudaGetSymbolAddress((void**)&X1h, g_X1h);
    cudaGetSymbolAddress((void**)&Hh,  g_Hh);
    cudaGetSymbolAddress((void**)&Wqh, g_Wqh);
    cudaGetSymbolAddress((void**)&Wkh, g_Wkh);
    cudaGetSymbolAddress((void**)&Wvh, g_Wvh);
    cudaGetSymbolAddress((void**)&W1h, g_W1h);
    cudaGetSymbolAddress((void**)&W2h, g_W2h);

    cudaFuncSetAttribute(gemm_fp16<0,0>, cudaFuncAttributeMaxDynamicSharedMemorySize, GEMM_SMEM_BYTES);
    cudaFuncSetAttribute(gemm_fp16<0,1>, cudaFuncAttributeMaxDynamicSharedMemorySize, GEMM_SMEM_BYTES);
    cudaFuncSetAttribute(gemm_fp16<1,1>, cudaFuncAttributeMaxDynamicSharedMemorySize, GEMM_SMEM_BYTES);
    cudaFuncSetAttribute(window_attn_mma, cudaFuncAttributeMaxDynamicSharedMemorySize, AT_SMEM);

    const dim3 blk(256);

    // --- batched fp16 conversion of all GEMM operands (one launch) ---
    {
        const unsigned nx = (unsigned)((size_t)M * E_DIM / 4);        // 4M
        const unsigned nw = (unsigned)((size_t)E_DIM * E_DIM / 4);    // 256K
        const unsigned nf = (unsigned)((size_t)E_DIM * HID_DIM / 4);  // 1M
        ConvSegs cs;
        cs.src[0] = x;  cs.dst[0] = xh;
        cs.src[1] = Wq; cs.dst[1] = Wqh;
        cs.src[2] = Wk; cs.dst[2] = Wkh;
        cs.src[3] = Wv; cs.dst[3] = Wvh;
        cs.src[4] = W1; cs.dst[4] = W1h;
        cs.src[5] = W2; cs.dst[5] = W2h;
        unsigned acc = 0;
        const unsigned counts[6] = { nx, nw, nw, nw, nf, nf };
        for (int i = 0; i < 6; i++) { acc += counts[i]; cs.end[i] = acc; }
        to_half_batched<<<(acc + 255) / 256, blk>>>(cs, acc);
    }

    // Merged QKV projection -> fp16 Q/K/V
    GemmOuts qkv;
    qkv.B[0] = Wqh; qkv.B[1] = Wkh; qkv.B[2] = Wvh;
    qkv.bias[0] = bq; qkv.bias[1] = bk; qkv.bias[2] = bv;
    qkv.C[0] = Qh; qkv.C[1] = Kh; qkv.C[2] = Vh;
    gemm_fp16<0,1><<<dim3(E_DIM / 128, M / 128, 3), blk, GEMM_SMEM_BYTES>>>(xh, qkv, M, E_DIM, E_DIM);

    window_attn_mma<<<M / WSZ, blk, AT_SMEM>>>(Qh, Kh, Vh, Ap);
    add_ln<1><<<M / 8, blk>>>(x, Ap, g1, be1, X1p, X1h);

    // FFN1: A = fp16 X1, output H in fp16 (consumed by FFN2)
    GemmOuts f1; f1.B[0] = W1h; f1.bias[0] = b1; f1.C[0] = Hh;
    f1.B[1] = f1.B[2] = W1h; f1.bias[1] = f1.bias[2] = b1; f1.C[1] = f1.C[2] = Hh;
    gemm_fp16<1,1><<<dim3(HID_DIM / 128, M / 128, 1), blk, GEMM_SMEM_BYTES>>>(X1h, f1, M, HID_DIM, E_DIM);

    GemmOuts f2; f2.B[0] = W2h; f2.bias[0] = b2; f2.C[0] = Fp;
    f2.B[1] = f2.B[2] = W2h; f2.bias[1] = f2.bias[2] = b2; f2.C[1] = f2.C[2] = Fp;
    gemm_fp16<0,0><<<dim3(E_DIM / 128, M / 128, 1), blk, GEMM_SMEM_BYTES>>>(Hh, f2, M, E_DIM, HID_DIM);

    add_ln<0><<<M / 8, blk>>>(X1p, Fp, g2, be2, out, nullptr);
}

// round 12
// speedup vs baseline: 1.0529x; 1.0529x over previous
#include <cuda_runtime.h>
#include <cuda_fp16.h>
#include <cstdint>
#include <math.h>

// ---------------------------------------------------------------------------
// Problem constants
// ---------------------------------------------------------------------------
#define E_DIM   1024
#define HID_DIM 4096
#define WSZ     64
#define M_TOK   16384

// ---------------------------------------------------------------------------
// Scratch (__device__ globals; no allocation allowed)
// ---------------------------------------------------------------------------
__device__ float  g_AT [M_TOK * E_DIM];
__device__ float  g_X1 [M_TOK * E_DIM];
__device__ float  g_F  [M_TOK * E_DIM];
__device__ __half g_Qh [M_TOK * E_DIM];
__device__ __half g_Kh [M_TOK * E_DIM];
__device__ __half g_Vh [M_TOK * E_DIM];
__device__ __half g_xh [M_TOK * E_DIM];
__device__ __half g_X1h[M_TOK * E_DIM];
__device__ __half g_Hh [(size_t)M_TOK * HID_DIM];
__device__ __half g_Wqh[E_DIM * E_DIM];
__device__ __half g_Wkh[E_DIM * E_DIM];
__device__ __half g_Wvh[E_DIM * E_DIM];
__device__ __half g_W1h[(size_t)E_DIM * HID_DIM];
__device__ __half g_W2h[(size_t)E_DIM * HID_DIM];

// ---------------------------------------------------------------------------
// PTX helpers
// ---------------------------------------------------------------------------
__device__ __forceinline__ uint32_t smem_to_u32(const void* p) {
    uint32_t a;
    asm("{ .reg .u64 t; cvta.to.shared.u64 t, %1; cvt.u32.u64 %0, t; }"
        : "=r"(a) : "l"(p));
    return a;
}

#define CP_ASYNC16(saddr, gptr) \
    asm volatile("cp.async.cg.shared.global [%0], [%1], 16;" \
                 :: "r"(saddr), "l"(gptr))
#define CP_COMMIT() asm volatile("cp.async.commit_group;" ::: "memory")
#define CP_WAIT(n)  asm volatile("cp.async.wait_group %0;" :: "n"(n) : "memory")

#define LDMATRIX_X4(r0, r1, r2, r3, addr) \
    asm volatile("ldmatrix.sync.aligned.m8n8.x4.shared.b16 {%0,%1,%2,%3}, [%4];" \
                 : "=r"(r0), "=r"(r1), "=r"(r2), "=r"(r3) : "r"(addr))

#define LDMATRIX_X4_TRANS(r0, r1, r2, r3, addr) \
    asm volatile("ldmatrix.sync.aligned.m8n8.x4.trans.shared.b16 {%0,%1,%2,%3}, [%4];" \
                 : "=r"(r0), "=r"(r1), "=r"(r2), "=r"(r3) : "r"(addr))

__device__ __forceinline__ void mma_fp16(float* c, const uint32_t* a, const uint32_t* b) {
    asm volatile(
        "mma.sync.aligned.m16n8k16.row.col.f32.f16.f16.f32 "
        "{%0,%1,%2,%3}, {%4,%5,%6,%7}, {%8,%9}, {%0,%1,%2,%3};"
        : "+f"(c[0]), "+f"(c[1]), "+f"(c[2]), "+f"(c[3])
        : "r"(a[0]), "r"(a[1]), "r"(a[2]), "r"(a[3]), "r"(b[0]), "r"(b[1]));
}

// ---------------------------------------------------------------------------
// Elementwise f32 -> f16 conversion
// ---------------------------------------------------------------------------
__global__ __launch_bounds__(256)
void to_half_kernel(const float* __restrict__ in, __half* __restrict__ out, size_t n4)
{
    const size_t i = (size_t)blockIdx.x * 256 + threadIdx.x;
    if (i >= n4) return;
    const float4 v = ((const float4*)in)[i];
    __half2 h0 = __floats2half2_rn(v.x, v.y);
    __half2 h1 = __floats2half2_rn(v.z, v.w);
    uint2 pk;
    pk.x = *(uint32_t*)&h0;
    pk.y = *(uint32_t*)&h1;
    ((uint2*)out)[i] = pk;
}

// ---------------------------------------------------------------------------
// fp16 tensor-core GEMM (R10 winner, unchanged):
// 128x128x64 block tile, 256 threads (4x2 warps, 32x64 warp tile),
// 3-stage cp.async pipeline (BK=64), one barrier per iteration, 2 CTAs/SM.
// ---------------------------------------------------------------------------
#define A_STRIDE_H 72
#define B_STRIDE_H 136
#define A_TILE_BYTES (128 * A_STRIDE_H * 2)   // 18432
#define B_TILE_BYTES (64 * B_STRIDE_H * 2)    // 17408
#define STAGE_BYTES  (A_TILE_BYTES + B_TILE_BYTES)   // 35840
#define GEMM_SMEM_BYTES (3 * STAGE_BYTES)            // 107520

struct GemmOuts {
    const __half* B[3];
    const float*  bias[3];
    void*         C[3];
};

template<int RELU, int OUT_HALF>
__global__ __launch_bounds__(256, 2)
void gemm_fp16(const __half* __restrict__ A, GemmOuts io,
               int M, int N, int K)
{
    extern __shared__ char smem[];
    const uint32_t sbase = smem_to_u32(smem);

    const int tid = threadIdx.x;
    const int wid = tid >> 5;
    const int lane = tid & 31;
    const int g = lane >> 2;
    const int t = lane & 3;

    const int wm = wid & 3;
    const int wn = wid >> 2;

    const int m0 = blockIdx.y * 128;
    const int n0 = blockIdx.x * 128;
    const int z  = blockIdx.z;

    const __half* Bmat = io.B[z];
    const float*  bias = io.bias[z];

    const __half* Ag = A + (size_t)m0 * K;
    const __half* Bg = Bmat + n0;

    auto load_tile = [&](int k0, int stage) {
        const uint32_t aoff = sbase + (uint32_t)stage * STAGE_BYTES;
        const uint32_t boff = aoff + A_TILE_BYTES;
#pragma unroll
        for (int i = 0; i < 4; i++) {
            const int s = tid + i * 256;
            const int r = s >> 3, c8 = (s & 7) << 3;
            CP_ASYNC16(aoff + (uint32_t)(r * A_STRIDE_H + c8) * 2,
                       Ag + (size_t)r * K + k0 + c8);
        }
#pragma unroll
        for (int i = 0; i < 4; i++) {
            const int s = tid + i * 256;
            const int r = s >> 4, c8 = (s & 15) << 3;
            CP_ASYNC16(boff + (uint32_t)(r * B_STRIDE_H + c8) * 2,
                       Bg + (size_t)(k0 + r) * N + c8);
        }
        CP_COMMIT();
    };

    float acc[2][8][4];
#pragma unroll
    for (int mi = 0; mi < 2; mi++)
#pragma unroll
        for (int ni = 0; ni < 8; ni++)
#pragma unroll
            for (int j = 0; j < 4; j++) acc[mi][ni][j] = 0.f;

    const int NK = K >> 6;
    load_tile(0, 0);
    load_tile(64, 1);

    const int a_row = wm * 32 + (lane & 7) + ((lane >> 3) & 1) * 8;
    const int a_col = (lane >> 4) << 3;
    const int b_row = (lane & 7) + ((lane >> 3) & 1) * 8;
    const int b_col = wn * 64 + ((lane >> 4) << 3);

    for (int kt = 0; kt < NK; kt++) {
        CP_WAIT(1);
        __syncthreads();

        if (kt + 2 < NK) load_tile((kt + 2) << 6, (kt + 2) % 3);
        else CP_COMMIT();

        const uint32_t sA = sbase + (uint32_t)(kt % 3) * STAGE_BYTES;
        const uint32_t sB = sA + A_TILE_BYTES;

#pragma unroll
        for (int kk = 0; kk < 4; kk++) {
            uint32_t a[2][4];
#pragma unroll
            for (int mi = 0; mi < 2; mi++) {
                const uint32_t addr = sA +
                    (uint32_t)((a_row + mi * 16) * A_STRIDE_H + a_col + kk * 16) * 2;
                LDMATRIX_X4(a[mi][0], a[mi][1], a[mi][2], a[mi][3], addr);
            }
            uint32_t b[4][4];
#pragma unroll
            for (int ni4 = 0; ni4 < 4; ni4++) {
                const uint32_t addr = sB +
                    (uint32_t)((b_row + kk * 16) * B_STRIDE_H + b_col + ni4 * 16) * 2;
                LDMATRIX_X4_TRANS(b[ni4][0], b[ni4][1], b[ni4][2], b[ni4][3], addr);
            }
#pragma unroll
            for (int mi = 0; mi < 2; mi++)
#pragma unroll
                for (int ni = 0; ni < 8; ni++)
                    mma_fp16(acc[mi][ni], a[mi], &b[ni >> 1][(ni & 1) * 2]);
        }
    }

#pragma unroll
    for (int mi = 0; mi < 2; mi++) {
        const int row = m0 + wm * 32 + mi * 16 + g;
#pragma unroll
        for (int ni = 0; ni < 8; ni++) {
            const int col = n0 + wn * 64 + ni * 8 + t * 2;
            const float b0 = bias[col], b1 = bias[col + 1];
            float2 lo = make_float2(acc[mi][ni][0] + b0, acc[mi][ni][1] + b1);
            float2 hi = make_float2(acc[mi][ni][2] + b0, acc[mi][ni][3] + b1);
            if (RELU) {
                lo.x = fmaxf(lo.x, 0.f); lo.y = fmaxf(lo.y, 0.f);
                hi.x = fmaxf(hi.x, 0.f); hi.y = fmaxf(hi.y, 0.f);
            }
            if (OUT_HALF) {
                __half* Ch = (__half*)io.C[z];
                __half2 l2 = __floats2half2_rn(lo.x, lo.y);
                __half2 h2 = __floats2half2_rn(hi.x, hi.y);
                *(__half2*)(Ch + (size_t)row * N + col) = l2;
                *(__half2*)(Ch + (size_t)(row + 8) * N + col) = h2;
            } else {
                float* Cf = (float*)io.C[z];
                *(float2*)(Cf + (size_t)row * N + col) = lo;
                *(float2*)(Cf + (size_t)(row + 8) * N + col) = hi;
            }
        }
    }
}

// ---------------------------------------------------------------------------
// Tensor-core window attention (R10 winner, unchanged):
// one block per 64-token window, 8 warps, 64-wide QK streaming.
// ---------------------------------------------------------------------------
#define AT_S_STRIDE 68    // floats
#define AT_P_STRIDE 72    // halves
#define AT_QK_STRIDE 72   // halves
#define AT_V_STRIDE 136   // halves
#define AT_P_OFF (64 * AT_S_STRIDE * 4)                 // 17408
#define AT_U_OFF (AT_P_OFF + 64 * AT_P_STRIDE * 2)      // 26624
#define AT_Q_BYTES (64 * AT_QK_STRIDE * 2)              // 9216
#define AT_QK_STAGE (2 * AT_Q_BYTES)                    // 18432
#define AT_V_STAGE (64 * AT_V_STRIDE * 2)               // 17408
#define AT_SMEM (AT_U_OFF + 2 * AT_QK_STAGE)            // 63488

__global__ __launch_bounds__(256, 2)
void window_attn_mma(const __half* __restrict__ Qh, const __half* __restrict__ Kh,
                     const __half* __restrict__ Vh, float* __restrict__ O)
{
    extern __shared__ char smem[];
    const uint32_t sbase = smem_to_u32(smem);
    float* Sf = (float*)smem;

    const int tid = threadIdx.x;
    const int wid = tid >> 5;
    const int lane = tid & 31;
    const int g = lane >> 2, t = lane & 3;
    const int wm = wid & 3;
    const int wn = wid >> 2;

    const int w = blockIdx.x;
    const __half* Qw = Qh + (size_t)w * WSZ * E_DIM;
    const __half* Kw = Kh + (size_t)w * WSZ * E_DIM;
    const __half* Vw = Vh + (size_t)w * WSZ * E_DIM;
    float* Ow = O + (size_t)w * WSZ * E_DIM;

    const int lrow  = (lane & 7) + ((lane >> 3) & 1) * 8;
    const int lcol8 = (lane >> 4) << 3;

    // ---- Phase 1: S = Q K^T ----
    auto load_qk = [&](int kc, int st) {
        const uint32_t qoff = sbase + AT_U_OFF + (uint32_t)st * AT_QK_STAGE;
        const uint32_t koff = qoff + AT_Q_BYTES;
#pragma unroll
        for (int i = 0; i < 2; i++) {
            const int s = tid + i * 256;
            const int r = s >> 3, c8 = (s & 7) << 3;
            CP_ASYNC16(qoff + (uint32_t)(r * AT_QK_STRIDE + c8) * 2,
                       Qw + (size_t)r * E_DIM + kc * 64 + c8);
            CP_ASYNC16(koff + (uint32_t)(r * AT_QK_STRIDE + c8) * 2,
                       Kw + (size_t)r * E_DIM + kc * 64 + c8);
        }
        CP_COMMIT();
    };

    float accS[4][4];
#pragma unroll
    for (int nt = 0; nt < 4; nt++)
#pragma unroll
        for (int j = 0; j < 4; j++) accS[nt][j] = 0.f;

    load_qk(0, 0);
    for (int kc = 0; kc < 16; kc++) {
        if (kc < 15) { load_qk(kc + 1, (kc + 1) & 1); CP_WAIT(1); }
        else         { CP_WAIT(0); }
        __syncthreads();

        const uint32_t qs = sbase + AT_U_OFF + (uint32_t)(kc & 1) * AT_QK_STAGE;
        const uint32_t ks = qs + AT_Q_BYTES;

#pragma unroll
        for (int kt = 0; kt < 4; kt++) {
            uint32_t a[4];
            LDMATRIX_X4(a[0], a[1], a[2], a[3],
                qs + (uint32_t)((wm * 16 + lrow) * AT_QK_STRIDE + lcol8 + kt * 16) * 2);
            uint32_t b[2][4];
#pragma unroll
            for (int h = 0; h < 2; h++)
                LDMATRIX_X4(b[h][0], b[h][1], b[h][2], b[h][3],
                    ks + (uint32_t)((wn * 32 + h * 16 + lrow) * AT_QK_STRIDE + lcol8 + kt * 16) * 2);
#pragma unroll
            for (int nt = 0; nt < 4; nt++) {
                uint32_t bf[2] = { b[nt >> 1][nt & 1], b[nt >> 1][(nt & 1) + 2] };
                mma_fp16(accS[nt], a, bf);
            }
        }
        __syncthreads();
    }

    // scale & write S (fp32)
    const float SCALE = 0.03125f;  // 1024^-0.5
#pragma unroll
    for (int nt = 0; nt < 4; nt++) {
        const int row = wm * 16 + g;
        const int col = wn * 32 + nt * 8 + t * 2;
        Sf[row * AT_S_STRIDE + col]           = accS[nt][0] * SCALE;
        Sf[row * AT_S_STRIDE + col + 1]       = accS[nt][1] * SCALE;
        Sf[(row + 8) * AT_S_STRIDE + col]     = accS[nt][2] * SCALE;
        Sf[(row + 8) * AT_S_STRIDE + col + 1] = accS[nt][3] * SCALE;
    }
    __syncthreads();

    // ---- softmax (4 threads per row) -> P fp16 ----
    {
        const int row = tid >> 2;
        const int part = (tid & 3) << 4;
        float vb[16];
        float m = -1e30f;
#pragma unroll
        for (int j = 0; j < 16; j++) {
            vb[j] = Sf[row * AT_S_STRIDE + part + j];
            m = fmaxf(m, vb[j]);
        }
        m = fmaxf(m, __shfl_xor_sync(0xffffffffu, m, 1));
        m = fmaxf(m, __shfl_xor_sync(0xffffffffu, m, 2));
        float s = 0.f;
#pragma unroll
        for (int j = 0; j < 16; j++) { vb[j] = __expf(vb[j] - m); s += vb[j]; }
        s += __shfl_xor_sync(0xffffffffu, s, 1);
        s += __shfl_xor_sync(0xffffffffu, s, 2);
        const float inv = 1.f / s;
        __half* Ph = (__half*)(smem + AT_P_OFF);
#pragma unroll
        for (int j = 0; j < 16; j++)
            Ph[row * AT_P_STRIDE + part + j] = __float2half(vb[j] * inv);
    }
    __syncthreads();

    // ---- Phase 2: O = P V ----
    uint32_t pf[4][4];
#pragma unroll
    for (int kt = 0; kt < 4; kt++)
        LDMATRIX_X4(pf[kt][0], pf[kt][1], pf[kt][2], pf[kt][3],
            sbase + AT_P_OFF +
            (uint32_t)((wm * 16 + lrow) * AT_P_STRIDE + lcol8 + kt * 16) * 2);

    auto load_v = [&](int ec, int st) {
        const uint32_t voff = sbase + AT_U_OFF + (uint32_t)st * AT_V_STAGE;
#pragma unroll
        for (int i = 0; i < 4; i++) {
            const int s = tid + i * 256;
            const int r = s >> 4, c8 = (s & 15) << 3;
            CP_ASYNC16(voff + (uint32_t)(r * AT_V_STRIDE + c8) * 2,
                       Vw + (size_t)r * E_DIM + ec * 128 + c8);
        }
        CP_COMMIT();
    };

    load_v(0, 0);
    for (int ec = 0; ec < 8; ec++) {
        if (ec < 7) { load_v(ec + 1, (ec + 1) & 1); CP_WAIT(1); }
        else        { CP_WAIT(0); }
        __syncthreads();

        const uint32_t vs = sbase + AT_U_OFF + (uint32_t)(ec & 1) * AT_V_STAGE;
        float acc[8][4];
#pragma unroll
        for (int ni = 0; ni < 8; ni++)
#pragma unroll
            for (int j = 0; j < 4; j++) acc[ni][j] = 0.f;

#pragma unroll
        for (int kt = 0; kt < 4; kt++) {
#pragma unroll
            for (int nt4 = 0; nt4 < 4; nt4++) {
                uint32_t b[4];
                LDMATRIX_X4_TRANS(b[0], b[1], b[2], b[3],
                    vs + (uint32_t)((lrow + kt * 16) * AT_V_STRIDE +
                                    wn * 64 + lcol8 + nt4 * 16) * 2);
                mma_fp16(acc[2 * nt4],     pf[kt], &b[0]);
                mma_fp16(acc[2 * nt4 + 1], pf[kt], &b[2]);
            }
        }

#pragma unroll
        for (int ni = 0; ni < 8; ni++) {
            const int row = wm * 16 + g;
            const int col = ec * 128 + wn * 64 + ni * 8 + t * 2;
            *(float2*)(Ow + (size_t)row * E_DIM + col) =
                make_float2(acc[ni][0], acc[ni][1]);
            *(float2*)(Ow + (size_t)(row + 8) * E_DIM + col) =
                make_float2(acc[ni][2], acc[ni][3]);
        }
        __syncthreads();
    }
}

// ---------------------------------------------------------------------------
// out = LayerNorm(A + B) * g + be; optionally also out_h = f16(out)
// Warp-per-row (R11 measured-good): 8 rows per 256-thread block, shfl-only.
// ---------------------------------------------------------------------------
template<int DUAL>
__global__ __launch_bounds__(256)
void add_ln(const float* __restrict__ A, const float* __restrict__ B,
            const float* __restrict__ g, const float* __restrict__ be,
            float* __restrict__ out, __half* __restrict__ out_h)
{
    const int warp = threadIdx.x >> 5;
    const int lane = threadIdx.x & 31;
    const int row = blockIdx.x * 8 + warp;

    const float* Ar = A + (size_t)row * E_DIM;
    const float* Br = B + (size_t)row * E_DIM;

    float4 vv[8];
    float s = 0.f, sq = 0.f;
#pragma unroll
    for (int k = 0; k < 8; k++) {
        const int col = k * 128 + lane * 4;
        const float4 a = *(const float4*)(Ar + col);
        const float4 b = *(const float4*)(Br + col);
        float4 v;
        v.x = a.x + b.x; v.y = a.y + b.y; v.z = a.z + b.z; v.w = a.w + b.w;
        vv[k] = v;
        s  += v.x + v.y + v.z + v.w;
        sq += v.x * v.x + v.y * v.y + v.z * v.z + v.w * v.w;
    }
#pragma unroll
    for (int o = 16; o > 0; o >>= 1) {
        s  += __shfl_xor_sync(0xffffffffu, s, o);
        sq += __shfl_xor_sync(0xffffffffu, sq, o);
    }
    const float mean = s * (1.f / E_DIM);
    const float var  = sq * (1.f / E_DIM) - mean * mean;
    const float rstd = rsqrtf(var + 1e-5f);

#pragma unroll
    for (int k = 0; k < 8; k++) {
        const int col = k * 128 + lane * 4;
        const float4 gg = *(const float4*)(g + col);
        const float4 bb = *(const float4*)(be + col);
        float4 o4;
        o4.x = (vv[k].x - mean) * rstd * gg.x + bb.x;
        o4.y = (vv[k].y - mean) * rstd * gg.y + bb.y;
        o4.z = (vv[k].z - mean) * rstd * gg.z + bb.z;
        o4.w = (vv[k].w - mean) * rstd * gg.w + bb.w;
        *(float4*)(out + (size_t)row * E_DIM + col) = o4;
        if (DUAL) {
            __half2 h0 = __floats2half2_rn(o4.x, o4.y);
            __half2 h1 = __floats2half2_rn(o4.z, o4.w);
            uint2 pk;
            pk.x = *(uint32_t*)&h0;
            pk.y = *(uint32_t*)&h1;
            *(uint2*)(out_h + (size_t)row * E_DIM + col) = pk;
        }
    }
}

// ---------------------------------------------------------------------------
extern "C" void kernel_launch(void* const* d_in, const int* in_sizes, int n_in,
                              void* d_out, int out_size)
{
    const float* x   = (const float*)d_in[0];
    const float* Wq  = (const float*)d_in[1];
    const float* bq  = (const float*)d_in[2];
    const float* Wk  = (const float*)d_in[3];
    const float* bk  = (const float*)d_in[4];
    const float* Wv  = (const float*)d_in[5];
    const float* bv  = (const float*)d_in[6];
    const float* g1  = (const float*)d_in[7];
    const float* be1 = (const float*)d_in[8];
    const float* W1  = (const float*)d_in[9];
    const float* b1  = (const float*)d_in[10];
    const float* W2  = (const float*)d_in[11];
    const float* b2  = (const float*)d_in[12];
    const float* g2  = (const float*)d_in[13];
    const float* be2 = (const float*)d_in[14];
    float* out = (float*)d_out;

    const int M = in_sizes[0] / E_DIM;   // 16384

    float *Ap, *X1p, *Fp;
    __half *Qh, *Kh, *Vh, *xh, *X1h, *Hh, *Wqh, *Wkh, *Wvh, *W1h, *W2h;
    cudaGetSymbolAddress((void**)&Ap,  g_AT);
    cudaGetSymbolAddress((void**)&X1p, g_X1);
    cudaGetSymbolAddress((void**)&Fp,  g_F);
    cudaGetSymbolAddress((void**)&Qh,  g_Qh);
    cudaGetSymbolAddress((void**)&Kh,  g_Kh);
    cudaGetSymbolAddress((void**)&Vh,  g_Vh);
    cudaGetSymbolAddress((void**)&xh,  g_xh);
    cudaGetSymbolAddress((void**)&X1h, g_X1h);
    cudaGetSymbolAddress((void**)&Hh,  g_Hh);
    cudaGetSymbolAddress((void**)&Wqh, g_Wqh);
    cudaGetSymbolAddress((void**)&Wkh, g_Wkh);
    cudaGetSymbolAddress((void**)&Wvh, g_Wvh);
    cudaGetSymbolAddress((void**)&W1h, g_W1h);
    cudaGetSymbolAddress((void**)&W2h, g_W2h);

    cudaFuncSetAttribute(gemm_fp16<0,0>, cudaFuncAttributeMaxDynamicSharedMemorySize, GEMM_SMEM_BYTES);
    cudaFuncSetAttribute(gemm_fp16<0,1>, cudaFuncAttributeMaxDynamicSharedMemorySize, GEMM_SMEM_BYTES);
    cudaFuncSetAttribute(gemm_fp16<1,1>, cudaFuncAttributeMaxDynamicSharedMemorySize, GEMM_SMEM_BYTES);
    cudaFuncSetAttribute(window_attn_mma, cudaFuncAttributeMaxDynamicSharedMemorySize, AT_SMEM);

    const dim3 blk(256);

    // --- fp16 conversion of GEMM operands (six plain launches, R10 style) ---
    {
        const size_t nx = (size_t)M * E_DIM / 4;
        to_half_kernel<<<(unsigned)((nx + 255) / 256), blk>>>(x, xh, nx);
        const size_t nw = (size_t)E_DIM * E_DIM / 4;
        to_half_kernel<<<(unsigned)((nw + 255) / 256), blk>>>(Wq, Wqh, nw);
        to_half_kernel<<<(unsigned)((nw + 255) / 256), blk>>>(Wk, Wkh, nw);
        to_half_kernel<<<(unsigned)((nw + 255) / 256), blk>>>(Wv, Wvh, nw);
        const size_t nf = (size_t)E_DIM * HID_DIM / 4;
        to_half_kernel<<<(unsigned)((nf + 255) / 256), blk>>>(W1, W1h, nf);
        to_half_kernel<<<(unsigned)((nf + 255) / 256), blk>>>(W2, W2h, nf);
    }

    // Merged QKV projection -> fp16 Q/K/V
    GemmOuts qkv;
    qkv.B[0] = Wqh; qkv.B[1] = Wkh; qkv.B[2] = Wvh;
    qkv.bias[0] = bq; qkv.bias[1] = bk; qkv.bias[2] = bv;
    qkv.C[0] = Qh; qkv.C[1] = Kh; qkv.C[2] = Vh;
    gemm_fp16<0,1><<<dim3(E_DIM / 128, M / 128, 3), blk, GEMM_SMEM_BYTES>>>(xh, qkv, M, E_DIM, E_DIM);

    window_attn_mma<<<M / WSZ, blk, AT_SMEM>>>(Qh, Kh, Vh, Ap);
    add_ln<1><<<M / 8, blk>>>(x, Ap, g1, be1, X1p, X1h);

    // FFN1: A = fp16 X1, output H in fp16 (consumed by FFN2)
    GemmOuts f1; f1.B[0] = W1h; f1.bias[0] = b1; f1.C[0] = Hh;
    f1.B[1] = f1.B[2] = W1h; f1.bias[1] = f1.bias[2] = b1; f1.C[1] = f1.C[2] = Hh;
    gemm_fp16<1,1><<<dim3(HID_DIM / 128, M / 128, 1), blk, GEMM_SMEM_BYTES>>>(X1h, f1, M, HID_DIM, E_DIM);

    GemmOuts f2; f2.B[0] = W2h; f2.bias[0] = b2; f2.C[0] = Fp;
    f2.B[1] = f2.B[2] = W2h; f2.bias[1] = f2.bias[2] = b2; f2.C[1] = f2.C[2] = Fp;
    gemm_fp16<0,0><<<dim3(E_DIM / 128, M / 128, 1), blk, GEMM_SMEM_BYTES>>>(Hh, f2, M, E_DIM, HID_DIM);

    add_ln<0><<<M / 8, blk>>>(X1p, Fp, g2, be2, out, nullptr);
}

// round 13
// speedup vs baseline: 1.0616x; 1.0083x over previous
#include <cuda_runtime.h>
#include <cuda_fp16.h>
#include <cstdint>
#include <math.h>

// ---------------------------------------------------------------------------
// Problem constants
// ---------------------------------------------------------------------------
#define E_DIM   1024
#define HID_DIM 4096
#define WSZ     64
#define M_TOK   16384

// ---------------------------------------------------------------------------
// Scratch (__device__ globals; no allocation allowed)
// ---------------------------------------------------------------------------
__device__ float  g_X1 [M_TOK * E_DIM];
__device__ __half g_ATh[M_TOK * E_DIM];
__device__ __half g_Fh [M_TOK * E_DIM];
__device__ __half g_Qh [M_TOK * E_DIM];
__device__ __half g_Kh [M_TOK * E_DIM];
__device__ __half g_Vh [M_TOK * E_DIM];
__device__ __half g_xh [M_TOK * E_DIM];
__device__ __half g_X1h[M_TOK * E_DIM];
__device__ __half g_Hh [(size_t)M_TOK * HID_DIM];
__device__ __half g_Wqh[E_DIM * E_DIM];
__device__ __half g_Wkh[E_DIM * E_DIM];
__device__ __half g_Wvh[E_DIM * E_DIM];
__device__ __half g_W1h[(size_t)E_DIM * HID_DIM];
__device__ __half g_W2h[(size_t)E_DIM * HID_DIM];

// ---------------------------------------------------------------------------
// PTX helpers
// ---------------------------------------------------------------------------
__device__ __forceinline__ uint32_t smem_to_u32(const void* p) {
    uint32_t a;
    asm("{ .reg .u64 t; cvta.to.shared.u64 t, %1; cvt.u32.u64 %0, t; }"
        : "=r"(a) : "l"(p));
    return a;
}

#define CP_ASYNC16(saddr, gptr) \
    asm volatile("cp.async.cg.shared.global [%0], [%1], 16;" \
                 :: "r"(saddr), "l"(gptr))
#define CP_COMMIT() asm volatile("cp.async.commit_group;" ::: "memory")
#define CP_WAIT(n)  asm volatile("cp.async.wait_group %0;" :: "n"(n) : "memory")

#define LDMATRIX_X4(r0, r1, r2, r3, addr) \
    asm volatile("ldmatrix.sync.aligned.m8n8.x4.shared.b16 {%0,%1,%2,%3}, [%4];" \
                 : "=r"(r0), "=r"(r1), "=r"(r2), "=r"(r3) : "r"(addr))

#define LDMATRIX_X4_TRANS(r0, r1, r2, r3, addr) \
    asm volatile("ldmatrix.sync.aligned.m8n8.x4.trans.shared.b16 {%0,%1,%2,%3}, [%4];" \
                 : "=r"(r0), "=r"(r1), "=r"(r2), "=r"(r3) : "r"(addr))

__device__ __forceinline__ void mma_fp16(float* c, const uint32_t* a, const uint32_t* b) {
    asm volatile(
        "mma.sync.aligned.m16n8k16.row.col.f32.f16.f16.f32 "
        "{%0,%1,%2,%3}, {%4,%5,%6,%7}, {%8,%9}, {%0,%1,%2,%3};"
        : "+f"(c[0]), "+f"(c[1]), "+f"(c[2]), "+f"(c[3])
        : "r"(a[0]), "r"(a[1]), "r"(a[2]), "r"(a[3]), "r"(b[0]), "r"(b[1]));
}

// ---------------------------------------------------------------------------
// Elementwise f32 -> f16 conversion
// ---------------------------------------------------------------------------
__global__ __launch_bounds__(256)
void to_half_kernel(const float* __restrict__ in, __half* __restrict__ out, size_t n4)
{
    const size_t i = (size_t)blockIdx.x * 256 + threadIdx.x;
    if (i >= n4) return;
    const float4 v = ((const float4*)in)[i];
    __half2 h0 = __floats2half2_rn(v.x, v.y);
    __half2 h1 = __floats2half2_rn(v.z, v.w);
    uint2 pk;
    pk.x = *(uint32_t*)&h0;
    pk.y = *(uint32_t*)&h1;
    ((uint2*)out)[i] = pk;
}

// ---------------------------------------------------------------------------
// fp16 tensor-core GEMM (R10 winner, unchanged):
// 128x128x64 block tile, 256 threads (4x2 warps, 32x64 warp tile),
// 3-stage cp.async pipeline (BK=64), one barrier per iteration, 2 CTAs/SM.
// ---------------------------------------------------------------------------
#define A_STRIDE_H 72
#define B_STRIDE_H 136
#define A_TILE_BYTES (128 * A_STRIDE_H * 2)   // 18432
#define B_TILE_BYTES (64 * B_STRIDE_H * 2)    // 17408
#define STAGE_BYTES  (A_TILE_BYTES + B_TILE_BYTES)   // 35840
#define GEMM_SMEM_BYTES (3 * STAGE_BYTES)            // 107520

struct GemmOuts {
    const __half* B[3];
    const float*  bias[3];
    void*         C[3];
};

template<int RELU, int OUT_HALF>
__global__ __launch_bounds__(256, 2)
void gemm_fp16(const __half* __restrict__ A, GemmOuts io,
               int M, int N, int K)
{
    extern __shared__ char smem[];
    const uint32_t sbase = smem_to_u32(smem);

    const int tid = threadIdx.x;
    const int wid = tid >> 5;
    const int lane = tid & 31;
    const int g = lane >> 2;
    const int t = lane & 3;

    const int wm = wid & 3;
    const int wn = wid >> 2;

    const int m0 = blockIdx.y * 128;
    const int n0 = blockIdx.x * 128;
    const int z  = blockIdx.z;

    const __half* Bmat = io.B[z];
    const float*  bias = io.bias[z];

    const __half* Ag = A + (size_t)m0 * K;
    const __half* Bg = Bmat + n0;

    auto load_tile = [&](int k0, int stage) {
        const uint32_t aoff = sbase + (uint32_t)stage * STAGE_BYTES;
        const uint32_t boff = aoff + A_TILE_BYTES;
#pragma unroll
        for (int i = 0; i < 4; i++) {
            const int s = tid + i * 256;
            const int r = s >> 3, c8 = (s & 7) << 3;
            CP_ASYNC16(aoff + (uint32_t)(r * A_STRIDE_H + c8) * 2,
                       Ag + (size_t)r * K + k0 + c8);
        }
#pragma unroll
        for (int i = 0; i < 4; i++) {
            const int s = tid + i * 256;
            const int r = s >> 4, c8 = (s & 15) << 3;
            CP_ASYNC16(boff + (uint32_t)(r * B_STRIDE_H + c8) * 2,
                       Bg + (size_t)(k0 + r) * N + c8);
        }
        CP_COMMIT();
    };

    float acc[2][8][4];
#pragma unroll
    for (int mi = 0; mi < 2; mi++)
#pragma unroll
        for (int ni = 0; ni < 8; ni++)
#pragma unroll
            for (int j = 0; j < 4; j++) acc[mi][ni][j] = 0.f;

    const int NK = K >> 6;
    load_tile(0, 0);
    load_tile(64, 1);

    const int a_row = wm * 32 + (lane & 7) + ((lane >> 3) & 1) * 8;
    const int a_col = (lane >> 4) << 3;
    const int b_row = (lane & 7) + ((lane >> 3) & 1) * 8;
    const int b_col = wn * 64 + ((lane >> 4) << 3);

    for (int kt = 0; kt < NK; kt++) {
        CP_WAIT(1);
        __syncthreads();

        if (kt + 2 < NK) load_tile((kt + 2) << 6, (kt + 2) % 3);
        else CP_COMMIT();

        const uint32_t sA = sbase + (uint32_t)(kt % 3) * STAGE_BYTES;
        const uint32_t sB = sA + A_TILE_BYTES;

#pragma unroll
        for (int kk = 0; kk < 4; kk++) {
            uint32_t a[2][4];
#pragma unroll
            for (int mi = 0; mi < 2; mi++) {
                const uint32_t addr = sA +
                    (uint32_t)((a_row + mi * 16) * A_STRIDE_H + a_col + kk * 16) * 2;
                LDMATRIX_X4(a[mi][0], a[mi][1], a[mi][2], a[mi][3], addr);
            }
            uint32_t b[4][4];
#pragma unroll
            for (int ni4 = 0; ni4 < 4; ni4++) {
                const uint32_t addr = sB +
                    (uint32_t)((b_row + kk * 16) * B_STRIDE_H + b_col + ni4 * 16) * 2;
                LDMATRIX_X4_TRANS(b[ni4][0], b[ni4][1], b[ni4][2], b[ni4][3], addr);
            }
#pragma unroll
            for (int mi = 0; mi < 2; mi++)
#pragma unroll
                for (int ni = 0; ni < 8; ni++)
                    mma_fp16(acc[mi][ni], a[mi], &b[ni >> 1][(ni & 1) * 2]);
        }
    }

#pragma unroll
    for (int mi = 0; mi < 2; mi++) {
        const int row = m0 + wm * 32 + mi * 16 + g;
#pragma unroll
        for (int ni = 0; ni < 8; ni++) {
            const int col = n0 + wn * 64 + ni * 8 + t * 2;
            const float b0 = bias[col], b1 = bias[col + 1];
            float2 lo = make_float2(acc[mi][ni][0] + b0, acc[mi][ni][1] + b1);
            float2 hi = make_float2(acc[mi][ni][2] + b0, acc[mi][ni][3] + b1);
            if (RELU) {
                lo.x = fmaxf(lo.x, 0.f); lo.y = fmaxf(lo.y, 0.f);
                hi.x = fmaxf(hi.x, 0.f); hi.y = fmaxf(hi.y, 0.f);
            }
            if (OUT_HALF) {
                __half* Ch = (__half*)io.C[z];
                __half2 l2 = __floats2half2_rn(lo.x, lo.y);
                __half2 h2 = __floats2half2_rn(hi.x, hi.y);
                *(__half2*)(Ch + (size_t)row * N + col) = l2;
                *(__half2*)(Ch + (size_t)(row + 8) * N + col) = h2;
            } else {
                float* Cf = (float*)io.C[z];
                *(float2*)(Cf + (size_t)row * N + col) = lo;
                *(float2*)(Cf + (size_t)(row + 8) * N + col) = hi;
            }
        }
    }
}

// ---------------------------------------------------------------------------
// Tensor-core window attention (R10 core, fp16 output):
// one block per 64-token window, 8 warps, 64-wide QK streaming.
// ---------------------------------------------------------------------------
#define AT_S_STRIDE 68    // floats
#define AT_P_STRIDE 72    // halves
#define AT_QK_STRIDE 72   // halves
#define AT_V_STRIDE 136   // halves
#define AT_P_OFF (64 * AT_S_STRIDE * 4)                 // 17408
#define AT_U_OFF (AT_P_OFF + 64 * AT_P_STRIDE * 2)      // 26624
#define AT_Q_BYTES (64 * AT_QK_STRIDE * 2)              // 9216
#define AT_QK_STAGE (2 * AT_Q_BYTES)                    // 18432
#define AT_V_STAGE (64 * AT_V_STRIDE * 2)               // 17408
#define AT_SMEM (AT_U_OFF + 2 * AT_QK_STAGE)            // 63488

__global__ __launch_bounds__(256, 2)
void window_attn_mma(const __half* __restrict__ Qh, const __half* __restrict__ Kh,
                     const __half* __restrict__ Vh, __half* __restrict__ O)
{
    extern __shared__ char smem[];
    const uint32_t sbase = smem_to_u32(smem);
    float* Sf = (float*)smem;

    const int tid = threadIdx.x;
    const int wid = tid >> 5;
    const int lane = tid & 31;
    const int g = lane >> 2, t = lane & 3;
    const int wm = wid & 3;
    const int wn = wid >> 2;

    const int w = blockIdx.x;
    const __half* Qw = Qh + (size_t)w * WSZ * E_DIM;
    const __half* Kw = Kh + (size_t)w * WSZ * E_DIM;
    const __half* Vw = Vh + (size_t)w * WSZ * E_DIM;
    __half* Ow = O + (size_t)w * WSZ * E_DIM;

    const int lrow  = (lane & 7) + ((lane >> 3) & 1) * 8;
    const int lcol8 = (lane >> 4) << 3;

    // ---- Phase 1: S = Q K^T ----
    auto load_qk = [&](int kc, int st) {
        const uint32_t qoff = sbase + AT_U_OFF + (uint32_t)st * AT_QK_STAGE;
        const uint32_t koff = qoff + AT_Q_BYTES;
#pragma unroll
        for (int i = 0; i < 2; i++) {
            const int s = tid + i * 256;
            const int r = s >> 3, c8 = (s & 7) << 3;
            CP_ASYNC16(qoff + (uint32_t)(r * AT_QK_STRIDE + c8) * 2,
                       Qw + (size_t)r * E_DIM + kc * 64 + c8);
            CP_ASYNC16(koff + (uint32_t)(r * AT_QK_STRIDE + c8) * 2,
                       Kw + (size_t)r * E_DIM + kc * 64 + c8);
        }
        CP_COMMIT();
    };

    float accS[4][4];
#pragma unroll
    for (int nt = 0; nt < 4; nt++)
#pragma unroll
        for (int j = 0; j < 4; j++) accS[nt][j] = 0.f;

    load_qk(0, 0);
    for (int kc = 0; kc < 16; kc++) {
        if (kc < 15) { load_qk(kc + 1, (kc + 1) & 1); CP_WAIT(1); }
        else         { CP_WAIT(0); }
        __syncthreads();

        const uint32_t qs = sbase + AT_U_OFF + (uint32_t)(kc & 1) * AT_QK_STAGE;
        const uint32_t ks = qs + AT_Q_BYTES;

#pragma unroll
        for (int kt = 0; kt < 4; kt++) {
            uint32_t a[4];
            LDMATRIX_X4(a[0], a[1], a[2], a[3],
                qs + (uint32_t)((wm * 16 + lrow) * AT_QK_STRIDE + lcol8 + kt * 16) * 2);
            uint32_t b[2][4];
#pragma unroll
            for (int h = 0; h < 2; h++)
                LDMATRIX_X4(b[h][0], b[h][1], b[h][2], b[h][3],
                    ks + (uint32_t)((wn * 32 + h * 16 + lrow) * AT_QK_STRIDE + lcol8 + kt * 16) * 2);
#pragma unroll
            for (int nt = 0; nt < 4; nt++) {
                uint32_t bf[2] = { b[nt >> 1][nt & 1], b[nt >> 1][(nt & 1) + 2] };
                mma_fp16(accS[nt], a, bf);
            }
        }
        __syncthreads();
    }

    // scale & write S (fp32)
    const float SCALE = 0.03125f;  // 1024^-0.5
#pragma unroll
    for (int nt = 0; nt < 4; nt++) {
        const int row = wm * 16 + g;
        const int col = wn * 32 + nt * 8 + t * 2;
        Sf[row * AT_S_STRIDE + col]           = accS[nt][0] * SCALE;
        Sf[row * AT_S_STRIDE + col + 1]       = accS[nt][1] * SCALE;
        Sf[(row + 8) * AT_S_STRIDE + col]     = accS[nt][2] * SCALE;
        Sf[(row + 8) * AT_S_STRIDE + col + 1] = accS[nt][3] * SCALE;
    }
    __syncthreads();

    // ---- softmax (4 threads per row) -> P fp16 ----
    {
        const int row = tid >> 2;
        const int part = (tid & 3) << 4;
        float vb[16];
        float m = -1e30f;
#pragma unroll
        for (int j = 0; j < 16; j++) {
            vb[j] = Sf[row * AT_S_STRIDE + part + j];
            m = fmaxf(m, vb[j]);
        }
        m = fmaxf(m, __shfl_xor_sync(0xffffffffu, m, 1));
        m = fmaxf(m, __shfl_xor_sync(0xffffffffu, m, 2));
        float s = 0.f;
#pragma unroll
        for (int j = 0; j < 16; j++) { vb[j] = __expf(vb[j] - m); s += vb[j]; }
        s += __shfl_xor_sync(0xffffffffu, s, 1);
        s += __shfl_xor_sync(0xffffffffu, s, 2);
        const float inv = 1.f / s;
        __half* Ph = (__half*)(smem + AT_P_OFF);
#pragma unroll
        for (int j = 0; j < 16; j++)
            Ph[row * AT_P_STRIDE + part + j] = __float2half(vb[j] * inv);
    }
    __syncthreads();

    // ---- Phase 2: O = P V ----
    uint32_t pf[4][4];
#pragma unroll
    for (int kt = 0; kt < 4; kt++)
        LDMATRIX_X4(pf[kt][0], pf[kt][1], pf[kt][2], pf[kt][3],
            sbase + AT_P_OFF +
            (uint32_t)((wm * 16 + lrow) * AT_P_STRIDE + lcol8 + kt * 16) * 2);

    auto load_v = [&](int ec, int st) {
        const uint32_t voff = sbase + AT_U_OFF + (uint32_t)st * AT_V_STAGE;
#pragma unroll
        for (int i = 0; i < 4; i++) {
            const int s = tid + i * 256;
            const int r = s >> 4, c8 = (s & 15) << 3;
            CP_ASYNC16(voff + (uint32_t)(r * AT_V_STRIDE + c8) * 2,
                       Vw + (size_t)r * E_DIM + ec * 128 + c8);
        }
        CP_COMMIT();
    };

    load_v(0, 0);
    for (int ec = 0; ec < 8; ec++) {
        if (ec < 7) { load_v(ec + 1, (ec + 1) & 1); CP_WAIT(1); }
        else        { CP_WAIT(0); }
        __syncthreads();

        const uint32_t vs = sbase + AT_U_OFF + (uint32_t)(ec & 1) * AT_V_STAGE;
        float acc[8][4];
#pragma unroll
        for (int ni = 0; ni < 8; ni++)
#pragma unroll
            for (int j = 0; j < 4; j++) acc[ni][j] = 0.f;

#pragma unroll
        for (int kt = 0; kt < 4; kt++) {
#pragma unroll
            for (int nt4 = 0; nt4 < 4; nt4++) {
                uint32_t b[4];
                LDMATRIX_X4_TRANS(b[0], b[1], b[2], b[3],
                    vs + (uint32_t)((lrow + kt * 16) * AT_V_STRIDE +
                                    wn * 64 + lcol8 + nt4 * 16) * 2);
                mma_fp16(acc[2 * nt4],     pf[kt], &b[0]);
                mma_fp16(acc[2 * nt4 + 1], pf[kt], &b[2]);
            }
        }

#pragma unroll
        for (int ni = 0; ni < 8; ni++) {
            const int row = wm * 16 + g;
            const int col = ec * 128 + wn * 64 + ni * 8 + t * 2;
            __half2 lo = __floats2half2_rn(acc[ni][0], acc[ni][1]);
            __half2 hi = __floats2half2_rn(acc[ni][2], acc[ni][3]);
            *(__half2*)(Ow + (size_t)row * E_DIM + col) = lo;
            *(__half2*)(Ow + (size_t)(row + 8) * E_DIM + col) = hi;
        }
        __syncthreads();
    }
}

// ---------------------------------------------------------------------------
// out = LayerNorm(A + B) * g + be; B is fp16; optionally also out_h = f16(out)
// Warp-per-row: 8 rows per 256-thread block, shfl-only reduction.
// ---------------------------------------------------------------------------
template<int DUAL>
__global__ __launch_bounds__(256)
void add_ln(const float* __restrict__ A, const __half* __restrict__ B,
            const float* __restrict__ g, const float* __restrict__ be,
            float* __restrict__ out, __half* __restrict__ out_h)
{
    const int warp = threadIdx.x >> 5;
    const int lane = threadIdx.x & 31;
    const int row = blockIdx.x * 8 + warp;

    const float*  Ar = A + (size_t)row * E_DIM;
    const __half* Br = B + (size_t)row * E_DIM;

    float4 vv[8];
    float s = 0.f, sq = 0.f;
#pragma unroll
    for (int k = 0; k < 8; k++) {
        const int col = k * 128 + lane * 4;
        const float4 a = *(const float4*)(Ar + col);
        const uint2 bp = *(const uint2*)(Br + col);
        const float2 b0 = __half22float2(*(const __half2*)&bp.x);
        const float2 b1 = __half22float2(*(const __half2*)&bp.y);
        float4 v;
        v.x = a.x + b0.x; v.y = a.y + b0.y; v.z = a.z + b1.x; v.w = a.w + b1.y;
        vv[k] = v;
        s  += v.x + v.y + v.z + v.w;
        sq += v.x * v.x + v.y * v.y + v.z * v.z + v.w * v.w;
    }
#pragma unroll
    for (int o = 16; o > 0; o >>= 1) {
        s  += __shfl_xor_sync(0xffffffffu, s, o);
        sq += __shfl_xor_sync(0xffffffffu, sq, o);
    }
    const float mean = s * (1.f / E_DIM);
    const float var  = sq * (1.f / E_DIM) - mean * mean;
    const float rstd = rsqrtf(var + 1e-5f);

#pragma unroll
    for (int k = 0; k < 8; k++) {
        const int col = k * 128 + lane * 4;
        const float4 gg = *(const float4*)(g + col);
        const float4 bb = *(const float4*)(be + col);
        float4 o4;
        o4.x = (vv[k].x - mean) * rstd * gg.x + bb.x;
        o4.y = (vv[k].y - mean) * rstd * gg.y + bb.y;
        o4.z = (vv[k].z - mean) * rstd * gg.z + bb.z;
        o4.w = (vv[k].w - mean) * rstd * gg.w + bb.w;
        *(float4*)(out + (size_t)row * E_DIM + col) = o4;
        if (DUAL) {
            __half2 h0 = __floats2half2_rn(o4.x, o4.y);
            __half2 h1 = __floats2half2_rn(o4.z, o4.w);
            uint2 pk;
            pk.x = *(uint32_t*)&h0;
            pk.y = *(uint32_t*)&h1;
            *(uint2*)(out_h + (size_t)row * E_DIM + col) = pk;
        }
    }
}

// ---------------------------------------------------------------------------
extern "C" void kernel_launch(void* const* d_in, const int* in_sizes, int n_in,
                              void* d_out, int out_size)
{
    const float* x   = (const float*)d_in[0];
    const float* Wq  = (const float*)d_in[1];
    const float* bq  = (const float*)d_in[2];
    const float* Wk  = (const float*)d_in[3];
    const float* bk  = (const float*)d_in[4];
    const float* Wv  = (const float*)d_in[5];
    const float* bv  = (const float*)d_in[6];
    const float* g1  = (const float*)d_in[7];
    const float* be1 = (const float*)d_in[8];
    const float* W1  = (const float*)d_in[9];
    const float* b1  = (const float*)d_in[10];
    const float* W2  = (const float*)d_in[11];
    const float* b2  = (const float*)d_in[12];
    const float* g2  = (const float*)d_in[13];
    const float* be2 = (const float*)d_in[14];
    float* out = (float*)d_out;

    const int M = in_sizes[0] / E_DIM;   // 16384

    float *X1p;
    __half *ATh, *Fh, *Qh, *Kh, *Vh, *xh, *X1h, *Hh, *Wqh, *Wkh, *Wvh, *W1h, *W2h;
    cudaGetSymbolAddress((void**)&X1p, g_X1);
    cudaGetSymbolAddress((void**)&ATh, g_ATh);
    cudaGetSymbolAddress((void**)&Fh,  g_Fh);
    cudaGetSymbolAddress((void**)&Qh,  g_Qh);
    cudaGetSymbolAddress((void**)&Kh,  g_Kh);
    cudaGetSymbolAddress((void**)&Vh,  g_Vh);
    cudaGetSymbolAddress((void**)&xh,  g_xh);
    cudaGetSymbolAddress((void**)&X1h, g_X1h);
    cudaGetSymbolAddress((void**)&Hh,  g_Hh);
    cudaGetSymbolAddress((void**)&Wqh, g_Wqh);
    cudaGetSymbolAddress((void**)&Wkh, g_Wkh);
    cudaGetSymbolAddress((void**)&Wvh, g_Wvh);
    cudaGetSymbolAddress((void**)&W1h, g_W1h);
    cudaGetSymbolAddress((void**)&W2h, g_W2h);

    cudaFuncSetAttribute(gemm_fp16<0,1>, cudaFuncAttributeMaxDynamicSharedMemorySize, GEMM_SMEM_BYTES);
    cudaFuncSetAttribute(gemm_fp16<1,1>, cudaFuncAttributeMaxDynamicSharedMemorySize, GEMM_SMEM_BYTES);
    cudaFuncSetAttribute(window_attn_mma, cudaFuncAttributeMaxDynamicSharedMemorySize, AT_SMEM);

    const dim3 blk(256);

    // --- fp16 conversion of GEMM operands ---
    {
        const size_t nx = (size_t)M * E_DIM / 4;
        to_half_kernel<<<(unsigned)((nx + 255) / 256), blk>>>(x, xh, nx);
        const size_t nw = (size_t)E_DIM * E_DIM / 4;
        to_half_kernel<<<(unsigned)((nw + 255) / 256), blk>>>(Wq, Wqh, nw);
        to_half_kernel<<<(unsigned)((nw + 255) / 256), blk>>>(Wk, Wkh, nw);
        to_half_kernel<<<(unsigned)((nw + 255) / 256), blk>>>(Wv, Wvh, nw);
        const size_t nf = (size_t)E_DIM * HID_DIM / 4;
        to_half_kernel<<<(unsigned)((nf + 255) / 256), blk>>>(W1, W1h, nf);
        to_half_kernel<<<(unsigned)((nf + 255) / 256), blk>>>(W2, W2h, nf);
    }

    // Merged QKV projection -> fp16 Q/K/V
    GemmOuts qkv;
    qkv.B[0] = Wqh; qkv.B[1] = Wkh; qkv.B[2] = Wvh;
    qkv.bias[0] = bq; qkv.bias[1] = bk; qkv.bias[2] = bv;
    qkv.C[0] = Qh; qkv.C[1] = Kh; qkv.C[2] = Vh;
    gemm_fp16<0,1><<<dim3(E_DIM / 128, M / 128, 3), blk, GEMM_SMEM_BYTES>>>(xh, qkv, M, E_DIM, E_DIM);

    window_attn_mma<<<M / WSZ, blk, AT_SMEM>>>(Qh, Kh, Vh, ATh);
    add_ln<1><<<M / 8, blk>>>(x, ATh, g1, be1, X1p, X1h);

    // FFN1: A = fp16 X1, output H in fp16 (consumed by FFN2)
    GemmOuts f1; f1.B[0] = W1h; f1.bias[0] = b1; f1.C[0] = Hh;
    f1.B[1] = f1.B[2] = W1h; f1.bias[1] = f1.bias[2] = b1; f1.C[1] = f1.C[2] = Hh;
    gemm_fp16<1,1><<<dim3(HID_DIM / 128, M / 128, 1), blk, GEMM_SMEM_BYTES>>>(X1h, f1, M, HID_DIM, E_DIM);

    // FFN2: output F in fp16 (consumed only by final add_ln)
    GemmOuts f2; f2.B[0] = W2h; f2.bias[0] = b2; f2.C[0] = Fh;
    f2.B[1] = f2.B[2] = W2h; f2.bias[1] = f2.bias[2] = b2; f2.C[1] = f2.C[2] = Fh;
    gemm_fp16<0,1><<<dim3(E_DIM / 128, M / 128, 1), blk, GEMM_SMEM_BYTES>>>(Hh, f2, M, E_DIM, HID_DIM);

    add_ln<0><<<M / 8, blk>>>(X1p, Fh, g2, be2, out, nullptr);
}

// round 14
// speedup vs baseline: 1.0620x; 1.0004x over previous
#include <cuda_runtime.h>
#include <cuda_fp16.h>
#include <cstdint>
#include <math.h>

// ---------------------------------------------------------------------------
// Problem constants
// ---------------------------------------------------------------------------
#define E_DIM   1024
#define HID_DIM 4096
#define WSZ     64
#define M_TOK   16384

// ---------------------------------------------------------------------------
// Scratch (__device__ globals; no allocation allowed)
// ---------------------------------------------------------------------------
__device__ float  g_X1 [M_TOK * E_DIM];
__device__ __half g_ATh[M_TOK * E_DIM];
__device__ __half g_Fh [M_TOK * E_DIM];
__device__ __half g_Qh [M_TOK * E_DIM];
__device__ __half g_Kh [M_TOK * E_DIM];
__device__ __half g_Vh [M_TOK * E_DIM];
__device__ __half g_xh [M_TOK * E_DIM];
__device__ __half g_X1h[M_TOK * E_DIM];
__device__ __half g_Hh [(size_t)M_TOK * HID_DIM];
__device__ __half g_Wqh[E_DIM * E_DIM];
__device__ __half g_Wkh[E_DIM * E_DIM];
__device__ __half g_Wvh[E_DIM * E_DIM];
__device__ __half g_W1h[(size_t)E_DIM * HID_DIM];
__device__ __half g_W2h[(size_t)E_DIM * HID_DIM];

// ---------------------------------------------------------------------------
// PTX helpers
// ---------------------------------------------------------------------------
__device__ __forceinline__ uint32_t smem_to_u32(const void* p) {
    uint32_t a;
    asm("{ .reg .u64 t; cvta.to.shared.u64 t, %1; cvt.u32.u64 %0, t; }"
        : "=r"(a) : "l"(p));
    return a;
}

#define CP_ASYNC16(saddr, gptr) \
    asm volatile("cp.async.cg.shared.global [%0], [%1], 16;" \
                 :: "r"(saddr), "l"(gptr))
#define CP_COMMIT() asm volatile("cp.async.commit_group;" ::: "memory")
#define CP_WAIT(n)  asm volatile("cp.async.wait_group %0;" :: "n"(n) : "memory")

#define LDMATRIX_X4(r0, r1, r2, r3, addr) \
    asm volatile("ldmatrix.sync.aligned.m8n8.x4.shared.b16 {%0,%1,%2,%3}, [%4];" \
                 : "=r"(r0), "=r"(r1), "=r"(r2), "=r"(r3) : "r"(addr))

#define LDMATRIX_X4_TRANS(r0, r1, r2, r3, addr) \
    asm volatile("ldmatrix.sync.aligned.m8n8.x4.trans.shared.b16 {%0,%1,%2,%3}, [%4];" \
                 : "=r"(r0), "=r"(r1), "=r"(r2), "=r"(r3) : "r"(addr))

__device__ __forceinline__ void mma_fp16(float* c, const uint32_t* a, const uint32_t* b) {
    asm volatile(
        "mma.sync.aligned.m16n8k16.row.col.f32.f16.f16.f32 "
        "{%0,%1,%2,%3}, {%4,%5,%6,%7}, {%8,%9}, {%0,%1,%2,%3};"
        : "+f"(c[0]), "+f"(c[1]), "+f"(c[2]), "+f"(c[3])
        : "r"(a[0]), "r"(a[1]), "r"(a[2]), "r"(a[3]), "r"(b[0]), "r"(b[1]));
}

// ---------------------------------------------------------------------------
// Elementwise f32 -> f16 conversion
// ---------------------------------------------------------------------------
__global__ __launch_bounds__(256)
void to_half_kernel(const float* __restrict__ in, __half* __restrict__ out, size_t n4)
{
    const size_t i = (size_t)blockIdx.x * 256 + threadIdx.x;
    if (i >= n4) return;
    const float4 v = ((const float4*)in)[i];
    __half2 h0 = __floats2half2_rn(v.x, v.y);
    __half2 h1 = __floats2half2_rn(v.z, v.w);
    uint2 pk;
    pk.x = *(uint32_t*)&h0;
    pk.y = *(uint32_t*)&h1;
    ((uint2*)out)[i] = pk;
}

// ---------------------------------------------------------------------------
// fp16 tensor-core GEMM (R10 winner, unchanged):
// 128x128x64 block tile, 256 threads (4x2 warps, 32x64 warp tile),
// 3-stage cp.async pipeline (BK=64), one barrier per iteration, 2 CTAs/SM.
// ---------------------------------------------------------------------------
#define A_STRIDE_H 72
#define B_STRIDE_H 136
#define A_TILE_BYTES (128 * A_STRIDE_H * 2)   // 18432
#define B_TILE_BYTES (64 * B_STRIDE_H * 2)    // 17408
#define STAGE_BYTES  (A_TILE_BYTES + B_TILE_BYTES)   // 35840
#define GEMM_SMEM_BYTES (3 * STAGE_BYTES)            // 107520

struct GemmOuts {
    const __half* B[3];
    const float*  bias[3];
    void*         C[3];
};

template<int RELU, int OUT_HALF>
__global__ __launch_bounds__(256, 2)
void gemm_fp16(const __half* __restrict__ A, GemmOuts io,
               int M, int N, int K)
{
    extern __shared__ char smem[];
    const uint32_t sbase = smem_to_u32(smem);

    const int tid = threadIdx.x;
    const int wid = tid >> 5;
    const int lane = tid & 31;
    const int g = lane >> 2;
    const int t = lane & 3;

    const int wm = wid & 3;
    const int wn = wid >> 2;

    const int m0 = blockIdx.y * 128;
    const int n0 = blockIdx.x * 128;
    const int z  = blockIdx.z;

    const __half* Bmat = io.B[z];
    const float*  bias = io.bias[z];

    const __half* Ag = A + (size_t)m0 * K;
    const __half* Bg = Bmat + n0;

    auto load_tile = [&](int k0, int stage) {
        const uint32_t aoff = sbase + (uint32_t)stage * STAGE_BYTES;
        const uint32_t boff = aoff + A_TILE_BYTES;
#pragma unroll
        for (int i = 0; i < 4; i++) {
            const int s = tid + i * 256;
            const int r = s >> 3, c8 = (s & 7) << 3;
            CP_ASYNC16(aoff + (uint32_t)(r * A_STRIDE_H + c8) * 2,
                       Ag + (size_t)r * K + k0 + c8);
        }
#pragma unroll
        for (int i = 0; i < 4; i++) {
            const int s = tid + i * 256;
            const int r = s >> 4, c8 = (s & 15) << 3;
            CP_ASYNC16(boff + (uint32_t)(r * B_STRIDE_H + c8) * 2,
                       Bg + (size_t)(k0 + r) * N + c8);
        }
        CP_COMMIT();
    };

    float acc[2][8][4];
#pragma unroll
    for (int mi = 0; mi < 2; mi++)
#pragma unroll
        for (int ni = 0; ni < 8; ni++)
#pragma unroll
            for (int j = 0; j < 4; j++) acc[mi][ni][j] = 0.f;

    const int NK = K >> 6;
    load_tile(0, 0);
    load_tile(64, 1);

    const int a_row = wm * 32 + (lane & 7) + ((lane >> 3) & 1) * 8;
    const int a_col = (lane >> 4) << 3;
    const int b_row = (lane & 7) + ((lane >> 3) & 1) * 8;
    const int b_col = wn * 64 + ((lane >> 4) << 3);

    for (int kt = 0; kt < NK; kt++) {
        CP_WAIT(1);
        __syncthreads();

        if (kt + 2 < NK) load_tile((kt + 2) << 6, (kt + 2) % 3);
        else CP_COMMIT();

        const uint32_t sA = sbase + (uint32_t)(kt % 3) * STAGE_BYTES;
        const uint32_t sB = sA + A_TILE_BYTES;

#pragma unroll
        for (int kk = 0; kk < 4; kk++) {
            uint32_t a[2][4];
#pragma unroll
            for (int mi = 0; mi < 2; mi++) {
                const uint32_t addr = sA +
                    (uint32_t)((a_row + mi * 16) * A_STRIDE_H + a_col + kk * 16) * 2;
                LDMATRIX_X4(a[mi][0], a[mi][1], a[mi][2], a[mi][3], addr);
            }
            uint32_t b[4][4];
#pragma unroll
            for (int ni4 = 0; ni4 < 4; ni4++) {
                const uint32_t addr = sB +
                    (uint32_t)((b_row + kk * 16) * B_STRIDE_H + b_col + ni4 * 16) * 2;
                LDMATRIX_X4_TRANS(b[ni4][0], b[ni4][1], b[ni4][2], b[ni4][3], addr);
            }
#pragma unroll
            for (int mi = 0; mi < 2; mi++)
#pragma unroll
                for (int ni = 0; ni < 8; ni++)
                    mma_fp16(acc[mi][ni], a[mi], &b[ni >> 1][(ni & 1) * 2]);
        }
    }

#pragma unroll
    for (int mi = 0; mi < 2; mi++) {
        const int row = m0 + wm * 32 + mi * 16 + g;
#pragma unroll
        for (int ni = 0; ni < 8; ni++) {
            const int col = n0 + wn * 64 + ni * 8 + t * 2;
            const float b0 = bias[col], b1 = bias[col + 1];
            float2 lo = make_float2(acc[mi][ni][0] + b0, acc[mi][ni][1] + b1);
            float2 hi = make_float2(acc[mi][ni][2] + b0, acc[mi][ni][3] + b1);
            if (RELU) {
                lo.x = fmaxf(lo.x, 0.f); lo.y = fmaxf(lo.y, 0.f);
                hi.x = fmaxf(hi.x, 0.f); hi.y = fmaxf(hi.y, 0.f);
            }
            if (OUT_HALF) {
                __half* Ch = (__half*)io.C[z];
                __half2 l2 = __floats2half2_rn(lo.x, lo.y);
                __half2 h2 = __floats2half2_rn(hi.x, hi.y);
                *(__half2*)(Ch + (size_t)row * N + col) = l2;
                *(__half2*)(Ch + (size_t)(row + 8) * N + col) = h2;
            } else {
                float* Cf = (float*)io.C[z];
                *(float2*)(Cf + (size_t)row * N + col) = lo;
                *(float2*)(Cf + (size_t)(row + 8) * N + col) = hi;
            }
        }
    }
}

// ---------------------------------------------------------------------------
// Tensor-core window attention (R10 core, fp16 output):
// one block per 64-token window, 8 warps, 64-wide QK streaming.
// ---------------------------------------------------------------------------
#define AT_S_STRIDE 68    // floats
#define AT_P_STRIDE 72    // halves
#define AT_QK_STRIDE 72   // halves
#define AT_V_STRIDE 136   // halves
#define AT_P_OFF (64 * AT_S_STRIDE * 4)                 // 17408
#define AT_U_OFF (AT_P_OFF + 64 * AT_P_STRIDE * 2)      // 26624
#define AT_Q_BYTES (64 * AT_QK_STRIDE * 2)              // 9216
#define AT_QK_STAGE (2 * AT_Q_BYTES)                    // 18432
#define AT_V_STAGE (64 * AT_V_STRIDE * 2)               // 17408
#define AT_SMEM (AT_U_OFF + 2 * AT_QK_STAGE)            // 63488

__global__ __launch_bounds__(256, 2)
void window_attn_mma(const __half* __restrict__ Qh, const __half* __restrict__ Kh,
                     const __half* __restrict__ Vh, __half* __restrict__ O)
{
    extern __shared__ char smem[];
    const uint32_t sbase = smem_to_u32(smem);
    float* Sf = (float*)smem;

    const int tid = threadIdx.x;
    const int wid = tid >> 5;
    const int lane = tid & 31;
    const int g = lane >> 2, t = lane & 3;
    const int wm = wid & 3;
    const int wn = wid >> 2;

    const int w = blockIdx.x;
    const __half* Qw = Qh + (size_t)w * WSZ * E_DIM;
    const __half* Kw = Kh + (size_t)w * WSZ * E_DIM;
    const __half* Vw = Vh + (size_t)w * WSZ * E_DIM;
    __half* Ow = O + (size_t)w * WSZ * E_DIM;

    const int lrow  = (lane & 7) + ((lane >> 3) & 1) * 8;
    const int lcol8 = (lane >> 4) << 3;

    // ---- Phase 1: S = Q K^T ----
    auto load_qk = [&](int kc, int st) {
        const uint32_t qoff = sbase + AT_U_OFF + (uint32_t)st * AT_QK_STAGE;
        const uint32_t koff = qoff + AT_Q_BYTES;
#pragma unroll
        for (int i = 0; i < 2; i++) {
            const int s = tid + i * 256;
            const int r = s >> 3, c8 = (s & 7) << 3;
            CP_ASYNC16(qoff + (uint32_t)(r * AT_QK_STRIDE + c8) * 2,
                       Qw + (size_t)r * E_DIM + kc * 64 + c8);
            CP_ASYNC16(koff + (uint32_t)(r * AT_QK_STRIDE + c8) * 2,
                       Kw + (size_t)r * E_DIM + kc * 64 + c8);
        }
        CP_COMMIT();
    };

    float accS[4][4];
#pragma unroll
    for (int nt = 0; nt < 4; nt++)
#pragma unroll
        for (int j = 0; j < 4; j++) accS[nt][j] = 0.f;

    load_qk(0, 0);
    for (int kc = 0; kc < 16; kc++) {
        if (kc < 15) { load_qk(kc + 1, (kc + 1) & 1); CP_WAIT(1); }
        else         { CP_WAIT(0); }
        __syncthreads();

        const uint32_t qs = sbase + AT_U_OFF + (uint32_t)(kc & 1) * AT_QK_STAGE;
        const uint32_t ks = qs + AT_Q_BYTES;

#pragma unroll
        for (int kt = 0; kt < 4; kt++) {
            uint32_t a[4];
            LDMATRIX_X4(a[0], a[1], a[2], a[3],
                qs + (uint32_t)((wm * 16 + lrow) * AT_QK_STRIDE + lcol8 + kt * 16) * 2);
            uint32_t b[2][4];
#pragma unroll
            for (int h = 0; h < 2; h++)
                LDMATRIX_X4(b[h][0], b[h][1], b[h][2], b[h][3],
                    ks + (uint32_t)((wn * 32 + h * 16 + lrow) * AT_QK_STRIDE + lcol8 + kt * 16) * 2);
#pragma unroll
            for (int nt = 0; nt < 4; nt++) {
                uint32_t bf[2] = { b[nt >> 1][nt & 1], b[nt >> 1][(nt & 1) + 2] };
                mma_fp16(accS[nt], a, bf);
            }
        }
        __syncthreads();
    }

    // scale & write S (fp32)
    const float SCALE = 0.03125f;  // 1024^-0.5
#pragma unroll
    for (int nt = 0; nt < 4; nt++) {
        const int row = wm * 16 + g;
        const int col = wn * 32 + nt * 8 + t * 2;
        Sf[row * AT_S_STRIDE + col]           = accS[nt][0] * SCALE;
        Sf[row * AT_S_STRIDE + col + 1]       = accS[nt][1] * SCALE;
        Sf[(row + 8) * AT_S_STRIDE + col]     = accS[nt][2] * SCALE;
        Sf[(row + 8) * AT_S_STRIDE + col + 1] = accS[nt][3] * SCALE;
    }
    __syncthreads();

    // ---- softmax (4 threads per row) -> P fp16 ----
    {
        const int row = tid >> 2;
        const int part = (tid & 3) << 4;
        float vb[16];
        float m = -1e30f;
#pragma unroll
        for (int j = 0; j < 16; j++) {
            vb[j] = Sf[row * AT_S_STRIDE + part + j];
            m = fmaxf(m, vb[j]);
        }
        m = fmaxf(m, __shfl_xor_sync(0xffffffffu, m, 1));
        m = fmaxf(m, __shfl_xor_sync(0xffffffffu, m, 2));
        float s = 0.f;
#pragma unroll
        for (int j = 0; j < 16; j++) { vb[j] = __expf(vb[j] - m); s += vb[j]; }
        s += __shfl_xor_sync(0xffffffffu, s, 1);
        s += __shfl_xor_sync(0xffffffffu, s, 2);
        const float inv = 1.f / s;
        __half* Ph = (__half*)(smem + AT_P_OFF);
#pragma unroll
        for (int j = 0; j < 16; j++)
            Ph[row * AT_P_STRIDE + part + j] = __float2half(vb[j] * inv);
    }
    __syncthreads();

    // ---- Phase 2: O = P V ----
    uint32_t pf[4][4];
#pragma unroll
    for (int kt = 0; kt < 4; kt++)
        LDMATRIX_X4(pf[kt][0], pf[kt][1], pf[kt][2], pf[kt][3],
            sbase + AT_P_OFF +
            (uint32_t)((wm * 16 + lrow) * AT_P_STRIDE + lcol8 + kt * 16) * 2);

    auto load_v = [&](int ec, int st) {
        const uint32_t voff = sbase + AT_U_OFF + (uint32_t)st * AT_V_STAGE;
#pragma unroll
        for (int i = 0; i < 4; i++) {
            const int s = tid + i * 256;
            const int r = s >> 4, c8 = (s & 15) << 3;
            CP_ASYNC16(voff + (uint32_t)(r * AT_V_STRIDE + c8) * 2,
                       Vw + (size_t)r * E_DIM + ec * 128 + c8);
        }
        CP_COMMIT();
    };

    load_v(0, 0);
    for (int ec = 0; ec < 8; ec++) {
        if (ec < 7) { load_v(ec + 1, (ec + 1) & 1); CP_WAIT(1); }
        else        { CP_WAIT(0); }
        __syncthreads();

        const uint32_t vs = sbase + AT_U_OFF + (uint32_t)(ec & 1) * AT_V_STAGE;
        float acc[8][4];
#pragma unroll
        for (int ni = 0; ni < 8; ni++)
#pragma unroll
            for (int j = 0; j < 4; j++) acc[ni][j] = 0.f;

#pragma unroll
        for (int kt = 0; kt < 4; kt++) {
#pragma unroll
            for (int nt4 = 0; nt4 < 4; nt4++) {
                uint32_t b[4];
                LDMATRIX_X4_TRANS(b[0], b[1], b[2], b[3],
                    vs + (uint32_t)((lrow + kt * 16) * AT_V_STRIDE +
                                    wn * 64 + lcol8 + nt4 * 16) * 2);
                mma_fp16(acc[2 * nt4],     pf[kt], &b[0]);
                mma_fp16(acc[2 * nt4 + 1], pf[kt], &b[2]);
            }
        }

#pragma unroll
        for (int ni = 0; ni < 8; ni++) {
            const int row = wm * 16 + g;
            const int col = ec * 128 + wn * 64 + ni * 8 + t * 2;
            __half2 lo = __floats2half2_rn(acc[ni][0], acc[ni][1]);
            __half2 hi = __floats2half2_rn(acc[ni][2], acc[ni][3]);
            *(__half2*)(Ow + (size_t)row * E_DIM + col) = lo;
            *(__half2*)(Ow + (size_t)(row + 8) * E_DIM + col) = hi;
        }
        __syncthreads();
    }
}

// ---------------------------------------------------------------------------
// out = LayerNorm(A + B) * g + be; B is fp16; optionally also out_h = f16(out)
// Warp-per-row: 8 rows per 256-thread block, shfl-only reduction.
// ---------------------------------------------------------------------------
template<int DUAL>
__global__ __launch_bounds__(256)
void add_ln(const float* __restrict__ A, const __half* __restrict__ B,
            const float* __restrict__ g, const float* __restrict__ be,
            float* __restrict__ out, __half* __restrict__ out_h)
{
    const int warp = threadIdx.x >> 5;
    const int lane = threadIdx.x & 31;
    const int row = blockIdx.x * 8 + warp;

    const float*  Ar = A + (size_t)row * E_DIM;
    const __half* Br = B + (size_t)row * E_DIM;

    float4 vv[8];
    float s = 0.f, sq = 0.f;
#pragma unroll
    for (int k = 0; k < 8; k++) {
        const int col = k * 128 + lane * 4;
        const float4 a = *(const float4*)(Ar + col);
        const uint2 bp = *(const uint2*)(Br + col);
        const float2 b0 = __half22float2(*(const __half2*)&bp.x);
        const float2 b1 = __half22float2(*(const __half2*)&bp.y);
        float4 v;
        v.x = a.x + b0.x; v.y = a.y + b0.y; v.z = a.z + b1.x; v.w = a.w + b1.y;
        vv[k] = v;
        s  += v.x + v.y + v.z + v.w;
        sq += v.x * v.x + v.y * v.y + v.z * v.z + v.w * v.w;
    }
#pragma unroll
    for (int o = 16; o > 0; o >>= 1) {
        s  += __shfl_xor_sync(0xffffffffu, s, o);
        sq += __shfl_xor_sync(0xffffffffu, sq, o);
    }
    const float mean = s * (1.f / E_DIM);
    const float var  = sq * (1.f / E_DIM) - mean * mean;
    const float rstd = rsqrtf(var + 1e-5f);

#pragma unroll
    for (int k = 0; k < 8; k++) {
        const int col = k * 128 + lane * 4;
        const float4 gg = *(const float4*)(g + col);
        const float4 bb = *(const float4*)(be + col);
        float4 o4;
        o4.x = (vv[k].x - mean) * rstd * gg.x + bb.x;
        o4.y = (vv[k].y - mean) * rstd * gg.y + bb.y;
        o4.z = (vv[k].z - mean) * rstd * gg.z + bb.z;
        o4.w = (vv[k].w - mean) * rstd * gg.w + bb.w;
        *(float4*)(out + (size_t)row * E_DIM + col) = o4;
        if (DUAL) {
            __half2 h0 = __floats2half2_rn(o4.x, o4.y);
            __half2 h1 = __floats2half2_rn(o4.z, o4.w);
            uint2 pk;
            pk.x = *(uint32_t*)&h0;
            pk.y = *(uint32_t*)&h1;
            *(uint2*)(out_h + (size_t)row * E_DIM + col) = pk;
        }
    }
}

// ---------------------------------------------------------------------------
extern "C" void kernel_launch(void* const* d_in, const int* in_sizes, int n_in,
                              void* d_out, int out_size)
{
    const float* x   = (const float*)d_in[0];
    const float* Wq  = (const float*)d_in[1];
    const float* bq  = (const float*)d_in[2];
    const float* Wk  = (const float*)d_in[3];
    const float* bk  = (const float*)d_in[4];
    const float* Wv  = (const float*)d_in[5];
    const float* bv  = (const float*)d_in[6];
    const float* g1  = (const float*)d_in[7];
    const float* be1 = (const float*)d_in[8];
    const float* W1  = (const float*)d_in[9];
    const float* b1  = (const float*)d_in[10];
    const float* W2  = (const float*)d_in[11];
    const float* b2  = (const float*)d_in[12];
    const float* g2  = (const float*)d_in[13];
    const float* be2 = (const float*)d_in[14];
    float* out = (float*)d_out;

    const int M = in_sizes[0] / E_DIM;   // 16384

    float *X1p;
    __half *ATh, *Fh, *Qh, *Kh, *Vh, *xh, *X1h, *Hh, *Wqh, *Wkh, *Wvh, *W1h, *W2h;
    cudaGetSymbolAddress((void**)&X1p, g_X1);
    cudaGetSymbolAddress((void**)&ATh, g_ATh);
    cudaGetSymbolAddress((void**)&Fh,  g_Fh);
    cudaGetSymbolAddress((void**)&Qh,  g_Qh);
    cudaGetSymbolAddress((void**)&Kh,  g_Kh);
    cudaGetSymbolAddress((void**)&Vh,  g_Vh);
    cudaGetSymbolAddress((void**)&xh,  g_xh);
    cudaGetSymbolAddress((void**)&X1h, g_X1h);
    cudaGetSymbolAddress((void**)&Hh,  g_Hh);
    cudaGetSymbolAddress((void**)&Wqh, g_Wqh);
    cudaGetSymbolAddress((void**)&Wkh, g_Wkh);
    cudaGetSymbolAddress((void**)&Wvh, g_Wvh);
    cudaGetSymbolAddress((void**)&W1h, g_W1h);
    cudaGetSymbolAddress((void**)&W2h, g_W2h);

    cudaFuncSetAttribute(gemm_fp16<0,1>, cudaFuncAttributeMaxDynamicSharedMemorySize, GEMM_SMEM_BYTES);
    cudaFuncSetAttribute(gemm_fp16<1,1>, cudaFuncAttributeMaxDynamicSharedMemorySize, GEMM_SMEM_BYTES);
    cudaFuncSetAttribute(window_attn_mma, cudaFuncAttributeMaxDynamicSharedMemorySize, AT_SMEM);

    const dim3 blk(256);

    // --- fp16 conversion of GEMM operands ---
    {
        const size_t nx = (size_t)M * E_DIM / 4;
        to_half_kernel<<<(unsigned)((nx + 255) / 256), blk>>>(x, xh, nx);
        const size_t nw = (size_t)E_DIM * E_DIM / 4;
        to_half_kernel<<<(unsigned)((nw + 255) / 256), blk>>>(Wq, Wqh, nw);
        to_half_kernel<<<(unsigned)((nw + 255) / 256), blk>>>(Wk, Wkh, nw);
        to_half_kernel<<<(unsigned)((nw + 255) / 256), blk>>>(Wv, Wvh, nw);
        const size_t nf = (size_t)E_DIM * HID_DIM / 4;
        to_half_kernel<<<(unsigned)((nf + 255) / 256), blk>>>(W1, W1h, nf);
        to_half_kernel<<<(unsigned)((nf + 255) / 256), blk>>>(W2, W2h, nf);
    }

    // Merged QKV projection -> fp16 Q/K/V
    GemmOuts qkv;
    qkv.B[0] = Wqh; qkv.B[1] = Wkh; qkv.B[2] = Wvh;
    qkv.bias[0] = bq; qkv.bias[1] = bk; qkv.bias[2] = bv;
    qkv.C[0] = Qh; qkv.C[1] = Kh; qkv.C[2] = Vh;
    gemm_fp16<0,1><<<dim3(E_DIM / 128, M / 128, 3), blk, GEMM_SMEM_BYTES>>>(xh, qkv, M, E_DIM, E_DIM);

    window_attn_mma<<<M / WSZ, blk, AT_SMEM>>>(Qh, Kh, Vh, ATh);
    add_ln<1><<<M / 8, blk>>>(x, ATh, g1, be1, X1p, X1h);

    // FFN1: A = fp16 X1, output H in fp16 (consumed by FFN2)
    GemmOuts f1; f1.B[0] = W1h; f1.bias[0] = b1; f1.C[0] = Hh;
    f1.B[1] = f1.B[2] = W1h; f1.bias[1] = f1.bias[2] = b1; f1.C[1] = f1.C[2] = Hh;
    gemm_fp16<1,1><<<dim3(HID_DIM / 128, M / 128, 1), blk, GEMM_SMEM_BYTES>>>(X1h, f1, M, HID_DIM, E_DIM);

    // FFN2: output F in fp16 (consumed only by final add_ln)
    GemmOuts f2; f2.B[0] = W2h; f2.bias[0] = b2; f2.C[0] = Fh;
    f2.B[1] = f2.B[2] = W2h; f2.bias[1] = f2.bias[2] = b2; f2.C[1] = f2.C[2] = Fh;
    gemm_fp16<0,1><<<dim3(E_DIM / 128, M / 128, 1), blk, GEMM_SMEM_BYTES>>>(Hh, f2, M, E_DIM, HID_DIM);

    add_ln<0><<<M / 8, blk>>>(X1p, Fh, g2, be2, out, nullptr);
}

// round 15
// speedup vs baseline: 1.0746x; 1.0118x over previous
#include <cuda_runtime.h>
#include <cuda_fp16.h>
#include <cstdint>
#include <math.h>

// ---------------------------------------------------------------------------
// Problem constants
// ---------------------------------------------------------------------------
#define E_DIM   1024
#define HID_DIM 4096
#define WSZ     64
#define M_TOK   16384

// ---------------------------------------------------------------------------
// Scratch (__device__ globals; no allocation allowed)
// ---------------------------------------------------------------------------
__device__ __half g_ATh[M_TOK * E_DIM];
__device__ __half g_Fh [M_TOK * E_DIM];
__device__ __half g_Qh [M_TOK * E_DIM];
__device__ __half g_Kh [M_TOK * E_DIM];
__device__ __half g_Vh [M_TOK * E_DIM];
__device__ __half g_xh [M_TOK * E_DIM];
__device__ __half g_X1h[M_TOK * E_DIM];
__device__ __half g_Hh [(size_t)M_TOK * HID_DIM];
__device__ __half g_Wqh[E_DIM * E_DIM];
__device__ __half g_Wkh[E_DIM * E_DIM];
__device__ __half g_Wvh[E_DIM * E_DIM];
__device__ __half g_W1h[(size_t)E_DIM * HID_DIM];
__device__ __half g_W2h[(size_t)E_DIM * HID_DIM];

// ---------------------------------------------------------------------------
// PTX helpers
// ---------------------------------------------------------------------------
__device__ __forceinline__ uint32_t smem_to_u32(const void* p) {
    uint32_t a;
    asm("{ .reg .u64 t; cvta.to.shared.u64 t, %1; cvt.u32.u64 %0, t; }"
        : "=r"(a) : "l"(p));
    return a;
}

#define CP_ASYNC16(saddr, gptr) \
    asm volatile("cp.async.cg.shared.global [%0], [%1], 16;" \
                 :: "r"(saddr), "l"(gptr))
#define CP_COMMIT() asm volatile("cp.async.commit_group;" ::: "memory")
#define CP_WAIT(n)  asm volatile("cp.async.wait_group %0;" :: "n"(n) : "memory")

#define LDMATRIX_X4(r0, r1, r2, r3, addr) \
    asm volatile("ldmatrix.sync.aligned.m8n8.x4.shared.b16 {%0,%1,%2,%3}, [%4];" \
                 : "=r"(r0), "=r"(r1), "=r"(r2), "=r"(r3) : "r"(addr))

#define LDMATRIX_X4_TRANS(r0, r1, r2, r3, addr) \
    asm volatile("ldmatrix.sync.aligned.m8n8.x4.trans.shared.b16 {%0,%1,%2,%3}, [%4];" \
                 : "=r"(r0), "=r"(r1), "=r"(r2), "=r"(r3) : "r"(addr))

__device__ __forceinline__ void mma_fp16(float* c, const uint32_t* a, const uint32_t* b) {
    asm volatile(
        "mma.sync.aligned.m16n8k16.row.col.f32.f16.f16.f32 "
        "{%0,%1,%2,%3}, {%4,%5,%6,%7}, {%8,%9}, {%0,%1,%2,%3};"
        : "+f"(c[0]), "+f"(c[1]), "+f"(c[2]), "+f"(c[3])
        : "r"(a[0]), "r"(a[1]), "r"(a[2]), "r"(a[3]), "r"(b[0]), "r"(b[1]));
}

// ---------------------------------------------------------------------------
// Elementwise f32 -> f16 conversion
// ---------------------------------------------------------------------------
__global__ __launch_bounds__(256)
void to_half_kernel(const float* __restrict__ in, __half* __restrict__ out, size_t n4)
{
    const size_t i = (size_t)blockIdx.x * 256 + threadIdx.x;
    if (i >= n4) return;
    const float4 v = ((const float4*)in)[i];
    __half2 h0 = __floats2half2_rn(v.x, v.y);
    __half2 h1 = __floats2half2_rn(v.z, v.w);
    uint2 pk;
    pk.x = *(uint32_t*)&h0;
    pk.y = *(uint32_t*)&h1;
    ((uint2*)out)[i] = pk;
}

// ---------------------------------------------------------------------------
// fp16 tensor-core GEMM (R10 winner, unchanged):
// 128x128x64 block tile, 256 threads (4x2 warps, 32x64 warp tile),
// 3-stage cp.async pipeline (BK=64), one barrier per iteration, 2 CTAs/SM.
// ---------------------------------------------------------------------------
#define A_STRIDE_H 72
#define B_STRIDE_H 136
#define A_TILE_BYTES (128 * A_STRIDE_H * 2)   // 18432
#define B_TILE_BYTES (64 * B_STRIDE_H * 2)    // 17408
#define STAGE_BYTES  (A_TILE_BYTES + B_TILE_BYTES)   // 35840
#define GEMM_SMEM_BYTES (3 * STAGE_BYTES)            // 107520

struct GemmOuts {
    const __half* B[3];
    const float*  bias[3];
    void*         C[3];
};

template<int RELU, int OUT_HALF>
__global__ __launch_bounds__(256, 2)
void gemm_fp16(const __half* __restrict__ A, GemmOuts io,
               int M, int N, int K)
{
    extern __shared__ char smem[];
    const uint32_t sbase = smem_to_u32(smem);

    const int tid = threadIdx.x;
    const int wid = tid >> 5;
    const int lane = tid & 31;
    const int g = lane >> 2;
    const int t = lane & 3;

    const int wm = wid & 3;
    const int wn = wid >> 2;

    const int m0 = blockIdx.y * 128;
    const int n0 = blockIdx.x * 128;
    const int z  = blockIdx.z;

    const __half* Bmat = io.B[z];
    const float*  bias = io.bias[z];

    const __half* Ag = A + (size_t)m0 * K;
    const __half* Bg = Bmat + n0;

    auto load_tile = [&](int k0, int stage) {
        const uint32_t aoff = sbase + (uint32_t)stage * STAGE_BYTES;
        const uint32_t boff = aoff + A_TILE_BYTES;
#pragma unroll
        for (int i = 0; i < 4; i++) {
            const int s = tid + i * 256;
            const int r = s >> 3, c8 = (s & 7) << 3;
            CP_ASYNC16(aoff + (uint32_t)(r * A_STRIDE_H + c8) * 2,
                       Ag + (size_t)r * K + k0 + c8);
        }
#pragma unroll
        for (int i = 0; i < 4; i++) {
            const int s = tid + i * 256;
            const int r = s >> 4, c8 = (s & 15) << 3;
            CP_ASYNC16(boff + (uint32_t)(r * B_STRIDE_H + c8) * 2,
                       Bg + (size_t)(k0 + r) * N + c8);
        }
        CP_COMMIT();
    };

    float acc[2][8][4];
#pragma unroll
    for (int mi = 0; mi < 2; mi++)
#pragma unroll
        for (int ni = 0; ni < 8; ni++)
#pragma unroll
            for (int j = 0; j < 4; j++) acc[mi][ni][j] = 0.f;

    const int NK = K >> 6;
    load_tile(0, 0);
    load_tile(64, 1);

    const int a_row = wm * 32 + (lane & 7) + ((lane >> 3) & 1) * 8;
    const int a_col = (lane >> 4) << 3;
    const int b_row = (lane & 7) + ((lane >> 3) & 1) * 8;
    const int b_col = wn * 64 + ((lane >> 4) << 3);

    for (int kt = 0; kt < NK; kt++) {
        CP_WAIT(1);
        __syncthreads();

        if (kt + 2 < NK) load_tile((kt + 2) << 6, (kt + 2) % 3);
        else CP_COMMIT();

        const uint32_t sA = sbase + (uint32_t)(kt % 3) * STAGE_BYTES;
        const uint32_t sB = sA + A_TILE_BYTES;

#pragma unroll
        for (int kk = 0; kk < 4; kk++) {
            uint32_t a[2][4];
#pragma unroll
            for (int mi = 0; mi < 2; mi++) {
                const uint32_t addr = sA +
                    (uint32_t)((a_row + mi * 16) * A_STRIDE_H + a_col + kk * 16) * 2;
                LDMATRIX_X4(a[mi][0], a[mi][1], a[mi][2], a[mi][3], addr);
            }
            uint32_t b[4][4];
#pragma unroll
            for (int ni4 = 0; ni4 < 4; ni4++) {
                const uint32_t addr = sB +
                    (uint32_t)((b_row + kk * 16) * B_STRIDE_H + b_col + ni4 * 16) * 2;
                LDMATRIX_X4_TRANS(b[ni4][0], b[ni4][1], b[ni4][2], b[ni4][3], addr);
            }
#pragma unroll
            for (int mi = 0; mi < 2; mi++)
#pragma unroll
                for (int ni = 0; ni < 8; ni++)
                    mma_fp16(acc[mi][ni], a[mi], &b[ni >> 1][(ni & 1) * 2]);
        }
    }

#pragma unroll
    for (int mi = 0; mi < 2; mi++) {
        const int row = m0 + wm * 32 + mi * 16 + g;
#pragma unroll
        for (int ni = 0; ni < 8; ni++) {
            const int col = n0 + wn * 64 + ni * 8 + t * 2;
            const float b0 = bias[col], b1 = bias[col + 1];
            float2 lo = make_float2(acc[mi][ni][0] + b0, acc[mi][ni][1] + b1);
            float2 hi = make_float2(acc[mi][ni][2] + b0, acc[mi][ni][3] + b1);
            if (RELU) {
                lo.x = fmaxf(lo.x, 0.f); lo.y = fmaxf(lo.y, 0.f);
                hi.x = fmaxf(hi.x, 0.f); hi.y = fmaxf(hi.y, 0.f);
            }
            if (OUT_HALF) {
                __half* Ch = (__half*)io.C[z];
                __half2 l2 = __floats2half2_rn(lo.x, lo.y);
                __half2 h2 = __floats2half2_rn(hi.x, hi.y);
                *(__half2*)(Ch + (size_t)row * N + col) = l2;
                *(__half2*)(Ch + (size_t)(row + 8) * N + col) = h2;
            } else {
                float* Cf = (float*)io.C[z];
                *(float2*)(Cf + (size_t)row * N + col) = lo;
                *(float2*)(Cf + (size_t)(row + 8) * N + col) = hi;
            }
        }
    }
}

// ---------------------------------------------------------------------------
// Tensor-core window attention (R14, unchanged): fp16 in/out.
// ---------------------------------------------------------------------------
#define AT_S_STRIDE 68    // floats
#define AT_P_STRIDE 72    // halves
#define AT_QK_STRIDE 72   // halves
#define AT_V_STRIDE 136   // halves
#define AT_P_OFF (64 * AT_S_STRIDE * 4)                 // 17408
#define AT_U_OFF (AT_P_OFF + 64 * AT_P_STRIDE * 2)      // 26624
#define AT_Q_BYTES (64 * AT_QK_STRIDE * 2)              // 9216
#define AT_QK_STAGE (2 * AT_Q_BYTES)                    // 18432
#define AT_V_STAGE (64 * AT_V_STRIDE * 2)               // 17408
#define AT_SMEM (AT_U_OFF + 2 * AT_QK_STAGE)            // 63488

__global__ __launch_bounds__(256, 2)
void window_attn_mma(const __half* __restrict__ Qh, const __half* __restrict__ Kh,
                     const __half* __restrict__ Vh, __half* __restrict__ O)
{
    extern __shared__ char smem[];
    const uint32_t sbase = smem_to_u32(smem);
    float* Sf = (float*)smem;

    const int tid = threadIdx.x;
    const int wid = tid >> 5;
    const int lane = tid & 31;
    const int g = lane >> 2, t = lane & 3;
    const int wm = wid & 3;
    const int wn = wid >> 2;

    const int w = blockIdx.x;
    const __half* Qw = Qh + (size_t)w * WSZ * E_DIM;
    const __half* Kw = Kh + (size_t)w * WSZ * E_DIM;
    const __half* Vw = Vh + (size_t)w * WSZ * E_DIM;
    __half* Ow = O + (size_t)w * WSZ * E_DIM;

    const int lrow  = (lane & 7) + ((lane >> 3) & 1) * 8;
    const int lcol8 = (lane >> 4) << 3;

    // ---- Phase 1: S = Q K^T ----
    auto load_qk = [&](int kc, int st) {
        const uint32_t qoff = sbase + AT_U_OFF + (uint32_t)st * AT_QK_STAGE;
        const uint32_t koff = qoff + AT_Q_BYTES;
#pragma unroll
        for (int i = 0; i < 2; i++) {
            const int s = tid + i * 256;
            const int r = s >> 3, c8 = (s & 7) << 3;
            CP_ASYNC16(qoff + (uint32_t)(r * AT_QK_STRIDE + c8) * 2,
                       Qw + (size_t)r * E_DIM + kc * 64 + c8);
            CP_ASYNC16(koff + (uint32_t)(r * AT_QK_STRIDE + c8) * 2,
                       Kw + (size_t)r * E_DIM + kc * 64 + c8);
        }
        CP_COMMIT();
    };

    float accS[4][4];
#pragma unroll
    for (int nt = 0; nt < 4; nt++)
#pragma unroll
        for (int j = 0; j < 4; j++) accS[nt][j] = 0.f;

    load_qk(0, 0);
    for (int kc = 0; kc < 16; kc++) {
        if (kc < 15) { load_qk(kc + 1, (kc + 1) & 1); CP_WAIT(1); }
        else         { CP_WAIT(0); }
        __syncthreads();

        const uint32_t qs = sbase + AT_U_OFF + (uint32_t)(kc & 1) * AT_QK_STAGE;
        const uint32_t ks = qs + AT_Q_BYTES;

#pragma unroll
        for (int kt = 0; kt < 4; kt++) {
            uint32_t a[4];
            LDMATRIX_X4(a[0], a[1], a[2], a[3],
                qs + (uint32_t)((wm * 16 + lrow) * AT_QK_STRIDE + lcol8 + kt * 16) * 2);
            uint32_t b[2][4];
#pragma unroll
            for (int h = 0; h < 2; h++)
                LDMATRIX_X4(b[h][0], b[h][1], b[h][2], b[h][3],
                    ks + (uint32_t)((wn * 32 + h * 16 + lrow) * AT_QK_STRIDE + lcol8 + kt * 16) * 2);
#pragma unroll
            for (int nt = 0; nt < 4; nt++) {
                uint32_t bf[2] = { b[nt >> 1][nt & 1], b[nt >> 1][(nt & 1) + 2] };
                mma_fp16(accS[nt], a, bf);
            }
        }
        __syncthreads();
    }

    // scale & write S (fp32)
    const float SCALE = 0.03125f;  // 1024^-0.5
#pragma unroll
    for (int nt = 0; nt < 4; nt++) {
        const int row = wm * 16 + g;
        const int col = wn * 32 + nt * 8 + t * 2;
        Sf[row * AT_S_STRIDE + col]           = accS[nt][0] * SCALE;
        Sf[row * AT_S_STRIDE + col + 1]       = accS[nt][1] * SCALE;
        Sf[(row + 8) * AT_S_STRIDE + col]     = accS[nt][2] * SCALE;
        Sf[(row + 8) * AT_S_STRIDE + col + 1] = accS[nt][3] * SCALE;
    }
    __syncthreads();

    // ---- softmax (4 threads per row) -> P fp16 ----
    {
        const int row = tid >> 2;
        const int part = (tid & 3) << 4;
        float vb[16];
        float m = -1e30f;
#pragma unroll
        for (int j = 0; j < 16; j++) {
            vb[j] = Sf[row * AT_S_STRIDE + part + j];
            m = fmaxf(m, vb[j]);
        }
        m = fmaxf(m, __shfl_xor_sync(0xffffffffu, m, 1));
        m = fmaxf(m, __shfl_xor_sync(0xffffffffu, m, 2));
        float s = 0.f;
#pragma unroll
        for (int j = 0; j < 16; j++) { vb[j] = __expf(vb[j] - m); s += vb[j]; }
        s += __shfl_xor_sync(0xffffffffu, s, 1);
        s += __shfl_xor_sync(0xffffffffu, s, 2);
        const float inv = 1.f / s;
        __half* Ph = (__half*)(smem + AT_P_OFF);
#pragma unroll
        for (int j = 0; j < 16; j++)
            Ph[row * AT_P_STRIDE + part + j] = __float2half(vb[j] * inv);
    }
    __syncthreads();

    // ---- Phase 2: O = P V ----
    uint32_t pf[4][4];
#pragma unroll
    for (int kt = 0; kt < 4; kt++)
        LDMATRIX_X4(pf[kt][0], pf[kt][1], pf[kt][2], pf[kt][3],
            sbase + AT_P_OFF +
            (uint32_t)((wm * 16 + lrow) * AT_P_STRIDE + lcol8 + kt * 16) * 2);

    auto load_v = [&](int ec, int st) {
        const uint32_t voff = sbase + AT_U_OFF + (uint32_t)st * AT_V_STAGE;
#pragma unroll
        for (int i = 0; i < 4; i++) {
            const int s = tid + i * 256;
            const int r = s >> 4, c8 = (s & 15) << 3;
            CP_ASYNC16(voff + (uint32_t)(r * AT_V_STRIDE + c8) * 2,
                       Vw + (size_t)r * E_DIM + ec * 128 + c8);
        }
        CP_COMMIT();
    };

    load_v(0, 0);
    for (int ec = 0; ec < 8; ec++) {
        if (ec < 7) { load_v(ec + 1, (ec + 1) & 1); CP_WAIT(1); }
        else        { CP_WAIT(0); }
        __syncthreads();

        const uint32_t vs = sbase + AT_U_OFF + (uint32_t)(ec & 1) * AT_V_STAGE;
        float acc[8][4];
#pragma unroll
        for (int ni = 0; ni < 8; ni++)
#pragma unroll
            for (int j = 0; j < 4; j++) acc[ni][j] = 0.f;

#pragma unroll
        for (int kt = 0; kt < 4; kt++) {
#pragma unroll
            for (int nt4 = 0; nt4 < 4; nt4++) {
                uint32_t b[4];
                LDMATRIX_X4_TRANS(b[0], b[1], b[2], b[3],
                    vs + (uint32_t)((lrow + kt * 16) * AT_V_STRIDE +
                                    wn * 64 + lcol8 + nt4 * 16) * 2);
                mma_fp16(acc[2 * nt4],     pf[kt], &b[0]);
                mma_fp16(acc[2 * nt4 + 1], pf[kt], &b[2]);
            }
        }

#pragma unroll
        for (int ni = 0; ni < 8; ni++) {
            const int row = wm * 16 + g;
            const int col = ec * 128 + wn * 64 + ni * 8 + t * 2;
            __half2 lo = __floats2half2_rn(acc[ni][0], acc[ni][1]);
            __half2 hi = __floats2half2_rn(acc[ni][2], acc[ni][3]);
            *(__half2*)(Ow + (size_t)row * E_DIM + col) = lo;
            *(__half2*)(Ow + (size_t)(row + 8) * E_DIM + col) = hi;
        }
        __syncthreads();
    }
}

// ---------------------------------------------------------------------------
// out = LayerNorm(A + B) * g + be
// A fp32 or fp16 (A_HALF); B fp16; writes fp32 out (WRITE_F32) and/or fp16
// out_h (WRITE_F16). Warp-per-row, shfl-only reduction.
// ---------------------------------------------------------------------------
template<int A_HALF, int WRITE_F32, int WRITE_F16>
__global__ __launch_bounds__(256)
void add_ln(const void* __restrict__ Av, const __half* __restrict__ B,
            const float* __restrict__ g, const float* __restrict__ be,
            float* __restrict__ out, __half* __restrict__ out_h)
{
    const int warp = threadIdx.x >> 5;
    const int lane = threadIdx.x & 31;
    const int row = blockIdx.x * 8 + warp;

    const __half* Br = B + (size_t)row * E_DIM;

    float4 vv[8];
    float s = 0.f, sq = 0.f;
#pragma unroll
    for (int k = 0; k < 8; k++) {
        const int col = k * 128 + lane * 4;
        float4 a;
        if (A_HALF) {
            const __half* Ar = (const __half*)Av + (size_t)row * E_DIM;
            const uint2 ap = *(const uint2*)(Ar + col);
            const float2 a0 = __half22float2(*(const __half2*)&ap.x);
            const float2 a1 = __half22float2(*(const __half2*)&ap.y);
            a = make_float4(a0.x, a0.y, a1.x, a1.y);
        } else {
            const float* Ar = (const float*)Av + (size_t)row * E_DIM;
            a = *(const float4*)(Ar + col);
        }
        const uint2 bp = *(const uint2*)(Br + col);
        const float2 b0 = __half22float2(*(const __half2*)&bp.x);
        const float2 b1 = __half22float2(*(const __half2*)&bp.y);
        float4 v;
        v.x = a.x + b0.x; v.y = a.y + b0.y; v.z = a.z + b1.x; v.w = a.w + b1.y;
        vv[k] = v;
        s  += v.x + v.y + v.z + v.w;
        sq += v.x * v.x + v.y * v.y + v.z * v.z + v.w * v.w;
    }
#pragma unroll
    for (int o = 16; o > 0; o >>= 1) {
        s  += __shfl_xor_sync(0xffffffffu, s, o);
        sq += __shfl_xor_sync(0xffffffffu, sq, o);
    }
    const float mean = s * (1.f / E_DIM);
    const float var  = sq * (1.f / E_DIM) - mean * mean;
    const float rstd = rsqrtf(var + 1e-5f);

#pragma unroll
    for (int k = 0; k < 8; k++) {
        const int col = k * 128 + lane * 4;
        const float4 gg = *(const float4*)(g + col);
        const float4 bb = *(const float4*)(be + col);
        float4 o4;
        o4.x = (vv[k].x - mean) * rstd * gg.x + bb.x;
        o4.y = (vv[k].y - mean) * rstd * gg.y + bb.y;
        o4.z = (vv[k].z - mean) * rstd * gg.z + bb.z;
        o4.w = (vv[k].w - mean) * rstd * gg.w + bb.w;
        if (WRITE_F32)
            *(float4*)(out + (size_t)row * E_DIM + col) = o4;
        if (WRITE_F16) {
            __half2 h0 = __floats2half2_rn(o4.x, o4.y);
            __half2 h1 = __floats2half2_rn(o4.z, o4.w);
            uint2 pk;
            pk.x = *(uint32_t*)&h0;
            pk.y = *(uint32_t*)&h1;
            *(uint2*)(out_h + (size_t)row * E_DIM + col) = pk;
        }
    }
}

// ---------------------------------------------------------------------------
extern "C" void kernel_launch(void* const* d_in, const int* in_sizes, int n_in,
                              void* d_out, int out_size)
{
    const float* x   = (const float*)d_in[0];
    const float* Wq  = (const float*)d_in[1];
    const float* bq  = (const float*)d_in[2];
    const float* Wk  = (const float*)d_in[3];
    const float* bk  = (const float*)d_in[4];
    const float* Wv  = (const float*)d_in[5];
    const float* bv  = (const float*)d_in[6];
    const float* g1  = (const float*)d_in[7];
    const float* be1 = (const float*)d_in[8];
    const float* W1  = (const float*)d_in[9];
    const float* b1  = (const float*)d_in[10];
    const float* W2  = (const float*)d_in[11];
    const float* b2  = (const float*)d_in[12];
    const float* g2  = (const float*)d_in[13];
    const float* be2 = (const float*)d_in[14];
    float* out = (float*)d_out;

    const int M = in_sizes[0] / E_DIM;   // 16384

    __half *ATh, *Fh, *Qh, *Kh, *Vh, *xh, *X1h, *Hh, *Wqh, *Wkh, *Wvh, *W1h, *W2h;
    cudaGetSymbolAddress((void**)&ATh, g_ATh);
    cudaGetSymbolAddress((void**)&Fh,  g_Fh);
    cudaGetSymbolAddress((void**)&Qh,  g_Qh);
    cudaGetSymbolAddress((void**)&Kh,  g_Kh);
    cudaGetSymbolAddress((void**)&Vh,  g_Vh);
    cudaGetSymbolAddress((void**)&xh,  g_xh);
    cudaGetSymbolAddress((void**)&X1h, g_X1h);
    cudaGetSymbolAddress((void**)&Hh,  g_Hh);
    cudaGetSymbolAddress((void**)&Wqh, g_Wqh);
    cudaGetSymbolAddress((void**)&Wkh, g_Wkh);
    cudaGetSymbolAddress((void**)&Wvh, g_Wvh);
    cudaGetSymbolAddress((void**)&W1h, g_W1h);
    cudaGetSymbolAddress((void**)&W2h, g_W2h);

    cudaFuncSetAttribute(gemm_fp16<0,1>, cudaFuncAttributeMaxDynamicSharedMemorySize, GEMM_SMEM_BYTES);
    cudaFuncSetAttribute(gemm_fp16<1,1>, cudaFuncAttributeMaxDynamicSharedMemorySize, GEMM_SMEM_BYTES);
    cudaFuncSetAttribute(window_attn_mma, cudaFuncAttributeMaxDynamicSharedMemorySize, AT_SMEM);

    const dim3 blk(256);

    // --- fp16 conversion of GEMM operands ---
    {
        const size_t nx = (size_t)M * E_DIM / 4;
        to_half_kernel<<<(unsigned)((nx + 255) / 256), blk>>>(x, xh, nx);
        const size_t nw = (size_t)E_DIM * E_DIM / 4;
        to_half_kernel<<<(unsigned)((nw + 255) / 256), blk>>>(Wq, Wqh, nw);
        to_half_kernel<<<(unsigned)((nw + 255) / 256), blk>>>(Wk, Wkh, nw);
        to_half_kernel<<<(unsigned)((nw + 255) / 256), blk>>>(Wv, Wvh, nw);
        const size_t nf = (size_t)E_DIM * HID_DIM / 4;
        to_half_kernel<<<(unsigned)((nf + 255) / 256), blk>>>(W1, W1h, nf);
        to_half_kernel<<<(unsigned)((nf + 255) / 256), blk>>>(W2, W2h, nf);
    }

    // Merged QKV projection -> fp16 Q/K/V
    GemmOuts qkv;
    qkv.B[0] = Wqh; qkv.B[1] = Wkh; qkv.B[2] = Wvh;
    qkv.bias[0] = bq; qkv.bias[1] = bk; qkv.bias[2] = bv;
    qkv.C[0] = Qh; qkv.C[1] = Kh; qkv.C[2] = Vh;
    gemm_fp16<0,1><<<dim3(E_DIM / 128, M / 128, 3), blk, GEMM_SMEM_BYTES>>>(xh, qkv, M, E_DIM, E_DIM);

    window_attn_mma<<<M / WSZ, blk, AT_SMEM>>>(Qh, Kh, Vh, ATh);

    // LN1: A = x (fp32), B = attention out (fp16) -> X1h (fp16 only)
    add_ln<0,0,1><<<M / 8, blk>>>(x, ATh, g1, be1, nullptr, X1h);

    // FFN1: A = fp16 X1, output H in fp16 (consumed by FFN2)
    GemmOuts f1; f1.B[0] = W1h; f1.bias[0] = b1; f1.C[0] = Hh;
    f1.B[1] = f1.B[2] = W1h; f1.bias[1] = f1.bias[2] = b1; f1.C[1] = f1.C[2] = Hh;
    gemm_fp16<1,1><<<dim3(HID_DIM / 128, M / 128, 1), blk, GEMM_SMEM_BYTES>>>(X1h, f1, M, HID_DIM, E_DIM);

    // FFN2: output F in fp16 (consumed only by final add_ln)
    GemmOuts f2; f2.B[0] = W2h; f2.bias[0] = b2; f2.C[0] = Fh;
    f2.B[1] = f2.B[2] = W2h; f2.bias[1] = f2.bias[2] = b2; f2.C[1] = f2.C[2] = Fh;
    gemm_fp16<0,1><<<dim3(E_DIM / 128, M / 128, 1), blk, GEMM_SMEM_BYTES>>>(Hh, f2, M, E_DIM, HID_DIM);

    // LN2: A = X1h (fp16 residual), B = Fh (fp16) -> fp32 out
    add_ln<1,1,0><<<M / 8, blk>>>(X1h, Fh, g2, be2, out, nullptr);
}

// round 16
// speedup vs baseline: 1.0797x; 1.0047x over previous
#include <cuda_runtime.h>
#include <cuda_fp16.h>
#include <cstdint>
#include <math.h>

// ---------------------------------------------------------------------------
// Problem constants
// ---------------------------------------------------------------------------
#define E_DIM   1024
#define HID_DIM 4096
#define WSZ     64
#define M_TOK   16384

// ---------------------------------------------------------------------------
// Scratch (__device__ globals; no allocation allowed)
// ---------------------------------------------------------------------------
__device__ __half g_ATh[M_TOK * E_DIM];
__device__ __half g_F0 [M_TOK * E_DIM];
__device__ __half g_F1 [M_TOK * E_DIM];
__device__ __half g_Qh [M_TOK * E_DIM];
__device__ __half g_Kh [M_TOK * E_DIM];
__device__ __half g_Vh [M_TOK * E_DIM];
__device__ __half g_xh [M_TOK * E_DIM];
__device__ __half g_X1h[M_TOK * E_DIM];
__device__ __half g_Hh [(size_t)M_TOK * HID_DIM];
__device__ __half g_Wqh[E_DIM * E_DIM];
__device__ __half g_Wkh[E_DIM * E_DIM];
__device__ __half g_Wvh[E_DIM * E_DIM];
__device__ __half g_W1h[(size_t)E_DIM * HID_DIM];
__device__ __half g_W2h[(size_t)E_DIM * HID_DIM];

// ---------------------------------------------------------------------------
// PTX helpers
// ---------------------------------------------------------------------------
__device__ __forceinline__ uint32_t smem_to_u32(const void* p) {
    uint32_t a;
    asm("{ .reg .u64 t; cvta.to.shared.u64 t, %1; cvt.u32.u64 %0, t; }"
        : "=r"(a) : "l"(p));
    return a;
}

#define CP_ASYNC16(saddr, gptr) \
    asm volatile("cp.async.cg.shared.global [%0], [%1], 16;" \
                 :: "r"(saddr), "l"(gptr))
#define CP_COMMIT() asm volatile("cp.async.commit_group;" ::: "memory")
#define CP_WAIT(n)  asm volatile("cp.async.wait_group %0;" :: "n"(n) : "memory")

#define LDMATRIX_X4(r0, r1, r2, r3, addr) \
    asm volatile("ldmatrix.sync.aligned.m8n8.x4.shared.b16 {%0,%1,%2,%3}, [%4];" \
                 : "=r"(r0), "=r"(r1), "=r"(r2), "=r"(r3) : "r"(addr))

#define LDMATRIX_X4_TRANS(r0, r1, r2, r3, addr) \
    asm volatile("ldmatrix.sync.aligned.m8n8.x4.trans.shared.b16 {%0,%1,%2,%3}, [%4];" \
                 : "=r"(r0), "=r"(r1), "=r"(r2), "=r"(r3) : "r"(addr))

__device__ __forceinline__ void mma_fp16(float* c, const uint32_t* a, const uint32_t* b) {
    asm volatile(
        "mma.sync.aligned.m16n8k16.row.col.f32.f16.f16.f32 "
        "{%0,%1,%2,%3}, {%4,%5,%6,%7}, {%8,%9}, {%0,%1,%2,%3};"
        : "+f"(c[0]), "+f"(c[1]), "+f"(c[2]), "+f"(c[3])
        : "r"(a[0]), "r"(a[1]), "r"(a[2]), "r"(a[3]), "r"(b[0]), "r"(b[1]));
}

// ---------------------------------------------------------------------------
// Elementwise f32 -> f16 conversion
// ---------------------------------------------------------------------------
__global__ __launch_bounds__(256)
void to_half_kernel(const float* __restrict__ in, __half* __restrict__ out, size_t n4)
{
    const size_t i = (size_t)blockIdx.x * 256 + threadIdx.x;
    if (i >= n4) return;
    const float4 v = ((const float4*)in)[i];
    __half2 h0 = __floats2half2_rn(v.x, v.y);
    __half2 h1 = __floats2half2_rn(v.z, v.w);
    uint2 pk;
    pk.x = *(uint32_t*)&h0;
    pk.y = *(uint32_t*)&h1;
    ((uint2*)out)[i] = pk;
}

// ---------------------------------------------------------------------------
// fp16 tensor-core GEMM: C = A[M, lda] (cols z*kz .. z*kz+K) @ B[K, N] (+bias)
// (optional ReLU; OUT_HALF stores fp16; BIAS=0 skips bias). fp32 accum.
// 128x128x64 block tile, 256 threads (4x2 warps, 32x64 warp tile),
// 3-stage cp.async pipeline (BK=64), one barrier per iteration, 2 CTAs/SM.
// blockIdx.z selects among up to 3 (B, bias, C) triples (merged QKV or split-K).
// ---------------------------------------------------------------------------
#define A_STRIDE_H 72
#define B_STRIDE_H 136
#define A_TILE_BYTES (128 * A_STRIDE_H * 2)   // 18432
#define B_TILE_BYTES (64 * B_STRIDE_H * 2)    // 17408
#define STAGE_BYTES  (A_TILE_BYTES + B_TILE_BYTES)   // 35840
#define GEMM_SMEM_BYTES (3 * STAGE_BYTES)            // 107520

struct GemmOuts {
    const __half* B[3];
    const float*  bias[3];
    void*         C[3];
};

template<int RELU, int OUT_HALF, int BIAS>
__global__ __launch_bounds__(256, 2)
void gemm_fp16(const __half* __restrict__ A, GemmOuts io,
               int M, int N, int K, int lda, int kz)
{
    extern __shared__ char smem[];
    const uint32_t sbase = smem_to_u32(smem);

    const int tid = threadIdx.x;
    const int wid = tid >> 5;
    const int lane = tid & 31;
    const int g = lane >> 2;
    const int t = lane & 3;

    const int wm = wid & 3;
    const int wn = wid >> 2;

    const int m0 = blockIdx.y * 128;
    const int n0 = blockIdx.x * 128;
    const int z  = blockIdx.z;

    const __half* Bmat = io.B[z];
    const float*  bias = io.bias[z];

    const __half* Ag = A + (size_t)m0 * lda + (size_t)z * kz;
    const __half* Bg = Bmat + n0;

    auto load_tile = [&](int k0, int stage) {
        const uint32_t aoff = sbase + (uint32_t)stage * STAGE_BYTES;
        const uint32_t boff = aoff + A_TILE_BYTES;
#pragma unroll
        for (int i = 0; i < 4; i++) {
            const int s = tid + i * 256;
            const int r = s >> 3, c8 = (s & 7) << 3;
            CP_ASYNC16(aoff + (uint32_t)(r * A_STRIDE_H + c8) * 2,
                       Ag + (size_t)r * lda + k0 + c8);
        }
#pragma unroll
        for (int i = 0; i < 4; i++) {
            const int s = tid + i * 256;
            const int r = s >> 4, c8 = (s & 15) << 3;
            CP_ASYNC16(boff + (uint32_t)(r * B_STRIDE_H + c8) * 2,
                       Bg + (size_t)(k0 + r) * N + c8);
        }
        CP_COMMIT();
    };

    float acc[2][8][4];
#pragma unroll
    for (int mi = 0; mi < 2; mi++)
#pragma unroll
        for (int ni = 0; ni < 8; ni++)
#pragma unroll
            for (int j = 0; j < 4; j++) acc[mi][ni][j] = 0.f;

    const int NK = K >> 6;
    load_tile(0, 0);
    load_tile(64, 1);

    const int a_row = wm * 32 + (lane & 7) + ((lane >> 3) & 1) * 8;
    const int a_col = (lane >> 4) << 3;
    const int b_row = (lane & 7) + ((lane >> 3) & 1) * 8;
    const int b_col = wn * 64 + ((lane >> 4) << 3);

    for (int kt = 0; kt < NK; kt++) {
        CP_WAIT(1);
        __syncthreads();

        if (kt + 2 < NK) load_tile((kt + 2) << 6, (kt + 2) % 3);
        else CP_COMMIT();

        const uint32_t sA = sbase + (uint32_t)(kt % 3) * STAGE_BYTES;
        const uint32_t sB = sA + A_TILE_BYTES;

#pragma unroll
        for (int kk = 0; kk < 4; kk++) {
            uint32_t a[2][4];
#pragma unroll
            for (int mi = 0; mi < 2; mi++) {
                const uint32_t addr = sA +
                    (uint32_t)((a_row + mi * 16) * A_STRIDE_H + a_col + kk * 16) * 2;
                LDMATRIX_X4(a[mi][0], a[mi][1], a[mi][2], a[mi][3], addr);
            }
            uint32_t b[4][4];
#pragma unroll
            for (int ni4 = 0; ni4 < 4; ni4++) {
                const uint32_t addr = sB +
                    (uint32_t)((b_row + kk * 16) * B_STRIDE_H + b_col + ni4 * 16) * 2;
                LDMATRIX_X4_TRANS(b[ni4][0], b[ni4][1], b[ni4][2], b[ni4][3], addr);
            }
#pragma unroll
            for (int mi = 0; mi < 2; mi++)
#pragma unroll
                for (int ni = 0; ni < 8; ni++)
                    mma_fp16(acc[mi][ni], a[mi], &b[ni >> 1][(ni & 1) * 2]);
        }
    }

#pragma unroll
    for (int mi = 0; mi < 2; mi++) {
        const int row = m0 + wm * 32 + mi * 16 + g;
#pragma unroll
        for (int ni = 0; ni < 8; ni++) {
            const int col = n0 + wn * 64 + ni * 8 + t * 2;
            float b0 = 0.f, b1 = 0.f;
            if (BIAS) { b0 = bias[col]; b1 = bias[col + 1]; }
            float2 lo = make_float2(acc[mi][ni][0] + b0, acc[mi][ni][1] + b1);
            float2 hi = make_float2(acc[mi][ni][2] + b0, acc[mi][ni][3] + b1);
            if (RELU) {
                lo.x = fmaxf(lo.x, 0.f); lo.y = fmaxf(lo.y, 0.f);
                hi.x = fmaxf(hi.x, 0.f); hi.y = fmaxf(hi.y, 0.f);
            }
            if (OUT_HALF) {
                __half* Ch = (__half*)io.C[z];
                __half2 l2 = __floats2half2_rn(lo.x, lo.y);
                __half2 h2 = __floats2half2_rn(hi.x, hi.y);
                *(__half2*)(Ch + (size_t)row * N + col) = l2;
                *(__half2*)(Ch + (size_t)(row + 8) * N + col) = h2;
            } else {
                float* Cf = (float*)io.C[z];
                *(float2*)(Cf + (size_t)row * N + col) = lo;
                *(float2*)(Cf + (size_t)(row + 8) * N + col) = hi;
            }
        }
    }
}

// ---------------------------------------------------------------------------
// Tensor-core window attention (R14, unchanged): fp16 in/out.
// ---------------------------------------------------------------------------
#define AT_S_STRIDE 68    // floats
#define AT_P_STRIDE 72    // halves
#define AT_QK_STRIDE 72   // halves
#define AT_V_STRIDE 136   // halves
#define AT_P_OFF (64 * AT_S_STRIDE * 4)                 // 17408
#define AT_U_OFF (AT_P_OFF + 64 * AT_P_STRIDE * 2)      // 26624
#define AT_Q_BYTES (64 * AT_QK_STRIDE * 2)              // 9216
#define AT_QK_STAGE (2 * AT_Q_BYTES)                    // 18432
#define AT_V_STAGE (64 * AT_V_STRIDE * 2)               // 17408
#define AT_SMEM (AT_U_OFF + 2 * AT_QK_STAGE)            // 63488

__global__ __launch_bounds__(256, 2)
void window_attn_mma(const __half* __restrict__ Qh, const __half* __restrict__ Kh,
                     const __half* __restrict__ Vh, __half* __restrict__ O)
{
    extern __shared__ char smem[];
    const uint32_t sbase = smem_to_u32(smem);
    float* Sf = (float*)smem;

    const int tid = threadIdx.x;
    const int wid = tid >> 5;
    const int lane = tid & 31;
    const int g = lane >> 2, t = lane & 3;
    const int wm = wid & 3;
    const int wn = wid >> 2;

    const int w = blockIdx.x;
    const __half* Qw = Qh + (size_t)w * WSZ * E_DIM;
    const __half* Kw = Kh + (size_t)w * WSZ * E_DIM;
    const __half* Vw = Vh + (size_t)w * WSZ * E_DIM;
    __half* Ow = O + (size_t)w * WSZ * E_DIM;

    const int lrow  = (lane & 7) + ((lane >> 3) & 1) * 8;
    const int lcol8 = (lane >> 4) << 3;

    // ---- Phase 1: S = Q K^T ----
    auto load_qk = [&](int kc, int st) {
        const uint32_t qoff = sbase + AT_U_OFF + (uint32_t)st * AT_QK_STAGE;
        const uint32_t koff = qoff + AT_Q_BYTES;
#pragma unroll
        for (int i = 0; i < 2; i++) {
            const int s = tid + i * 256;
            const int r = s >> 3, c8 = (s & 7) << 3;
            CP_ASYNC16(qoff + (uint32_t)(r * AT_QK_STRIDE + c8) * 2,
                       Qw + (size_t)r * E_DIM + kc * 64 + c8);
            CP_ASYNC16(koff + (uint32_t)(r * AT_QK_STRIDE + c8) * 2,
                       Kw + (size_t)r * E_DIM + kc * 64 + c8);
        }
        CP_COMMIT();
    };

    float accS[4][4];
#pragma unroll
    for (int nt = 0; nt < 4; nt++)
#pragma unroll
        for (int j = 0; j < 4; j++) accS[nt][j] = 0.f;

    load_qk(0, 0);
    for (int kc = 0; kc < 16; kc++) {
        if (kc < 15) { load_qk(kc + 1, (kc + 1) & 1); CP_WAIT(1); }
        else         { CP_WAIT(0); }
        __syncthreads();

        const uint32_t qs = sbase + AT_U_OFF + (uint32_t)(kc & 1) * AT_QK_STAGE;
        const uint32_t ks = qs + AT_Q_BYTES;

#pragma unroll
        for (int kt = 0; kt < 4; kt++) {
            uint32_t a[4];
            LDMATRIX_X4(a[0], a[1], a[2], a[3],
                qs + (uint32_t)((wm * 16 + lrow) * AT_QK_STRIDE + lcol8 + kt * 16) * 2);
            uint32_t b[2][4];
#pragma unroll
            for (int h = 0; h < 2; h++)
                LDMATRIX_X4(b[h][0], b[h][1], b[h][2], b[h][3],
                    ks + (uint32_t)((wn * 32 + h * 16 + lrow) * AT_QK_STRIDE + lcol8 + kt * 16) * 2);
#pragma unroll
            for (int nt = 0; nt < 4; nt++) {
                uint32_t bf[2] = { b[nt >> 1][nt & 1], b[nt >> 1][(nt & 1) + 2] };
                mma_fp16(accS[nt], a, bf);
            }
        }
        __syncthreads();
    }

    // scale & write S (fp32)
    const float SCALE = 0.03125f;  // 1024^-0.5
#pragma unroll
    for (int nt = 0; nt < 4; nt++) {
        const int row = wm * 16 + g;
        const int col = wn * 32 + nt * 8 + t * 2;
        Sf[row * AT_S_STRIDE + col]           = accS[nt][0] * SCALE;
        Sf[row * AT_S_STRIDE + col + 1]       = accS[nt][1] * SCALE;
        Sf[(row + 8) * AT_S_STRIDE + col]     = accS[nt][2] * SCALE;
        Sf[(row + 8) * AT_S_STRIDE + col + 1] = accS[nt][3] * SCALE;
    }
    __syncthreads();

    // ---- softmax (4 threads per row) -> P fp16 ----
    {
        const int row = tid >> 2;
        const int part = (tid & 3) << 4;
        float vb[16];
        float m = -1e30f;
#pragma unroll
        for (int j = 0; j < 16; j++) {
            vb[j] = Sf[row * AT_S_STRIDE + part + j];
            m = fmaxf(m, vb[j]);
        }
        m = fmaxf(m, __shfl_xor_sync(0xffffffffu, m, 1));
        m = fmaxf(m, __shfl_xor_sync(0xffffffffu, m, 2));
        float s = 0.f;
#pragma unroll
        for (int j = 0; j < 16; j++) { vb[j] = __expf(vb[j] - m); s += vb[j]; }
        s += __shfl_xor_sync(0xffffffffu, s, 1);
        s += __shfl_xor_sync(0xffffffffu, s, 2);
        const float inv = 1.f / s;
        __half* Ph = (__half*)(smem + AT_P_OFF);
#pragma unroll
        for (int j = 0; j < 16; j++)
            Ph[row * AT_P_STRIDE + part + j] = __float2half(vb[j] * inv);
    }
    __syncthreads();

    // ---- Phase 2: O = P V ----
    uint32_t pf[4][4];
#pragma unroll
    for (int kt = 0; kt < 4; kt++)
        LDMATRIX_X4(pf[kt][0], pf[kt][1], pf[kt][2], pf[kt][3],
            sbase + AT_P_OFF +
            (uint32_t)((wm * 16 + lrow) * AT_P_STRIDE + lcol8 + kt * 16) * 2);

    auto load_v = [&](int ec, int st) {
        const uint32_t voff = sbase + AT_U_OFF + (uint32_t)st * AT_V_STAGE;
#pragma unroll
        for (int i = 0; i < 4; i++) {
            const int s = tid + i * 256;
            const int r = s >> 4, c8 = (s & 15) << 3;
            CP_ASYNC16(voff + (uint32_t)(r * AT_V_STRIDE + c8) * 2,
                       Vw + (size_t)r * E_DIM + ec * 128 + c8);
        }
        CP_COMMIT();
    };

    load_v(0, 0);
    for (int ec = 0; ec < 8; ec++) {
        if (ec < 7) { load_v(ec + 1, (ec + 1) & 1); CP_WAIT(1); }
        else        { CP_WAIT(0); }
        __syncthreads();

        const uint32_t vs = sbase + AT_U_OFF + (uint32_t)(ec & 1) * AT_V_STAGE;
        float acc[8][4];
#pragma unroll
        for (int ni = 0; ni < 8; ni++)
#pragma unroll
            for (int j = 0; j < 4; j++) acc[ni][j] = 0.f;

#pragma unroll
        for (int kt = 0; kt < 4; kt++) {
#pragma unroll
            for (int nt4 = 0; nt4 < 4; nt4++) {
                uint32_t b[4];
                LDMATRIX_X4_TRANS(b[0], b[1], b[2], b[3],
                    vs + (uint32_t)((lrow + kt * 16) * AT_V_STRIDE +
                                    wn * 64 + lcol8 + nt4 * 16) * 2);
                mma_fp16(acc[2 * nt4],     pf[kt], &b[0]);
                mma_fp16(acc[2 * nt4 + 1], pf[kt], &b[2]);
            }
        }

#pragma unroll
        for (int ni = 0; ni < 8; ni++) {
            const int row = wm * 16 + g;
            const int col = ec * 128 + wn * 64 + ni * 8 + t * 2;
            __half2 lo = __floats2half2_rn(acc[ni][0], acc[ni][1]);
            __half2 hi = __floats2half2_rn(acc[ni][2], acc[ni][3]);
            *(__half2*)(Ow + (size_t)row * E_DIM + col) = lo;
            *(__half2*)(Ow + (size_t)(row + 8) * E_DIM + col) = hi;
        }
        __syncthreads();
    }
}

// ---------------------------------------------------------------------------
// LN1: out_h = f16( LayerNorm(A + B) * g + be ), A and B fp16.
// Warp-per-row, shfl-only reduction.
// ---------------------------------------------------------------------------
__global__ __launch_bounds__(256)
void add_ln1(const __half* __restrict__ A, const __half* __restrict__ B,
             const float* __restrict__ g, const float* __restrict__ be,
             __half* __restrict__ out_h)
{
    const int warp = threadIdx.x >> 5;
    const int lane = threadIdx.x & 31;
    const int row = blockIdx.x * 8 + warp;

    const __half* Ar = A + (size_t)row * E_DIM;
    const __half* Br = B + (size_t)row * E_DIM;

    float4 vv[8];
    float s = 0.f, sq = 0.f;
#pragma unroll
    for (int k = 0; k < 8; k++) {
        const int col = k * 128 + lane * 4;
        const uint2 ap = *(const uint2*)(Ar + col);
        const float2 a0 = __half22float2(*(const __half2*)&ap.x);
        const float2 a1 = __half22float2(*(const __half2*)&ap.y);
        const uint2 bp = *(const uint2*)(Br + col);
        const float2 b0 = __half22float2(*(const __half2*)&bp.x);
        const float2 b1 = __half22float2(*(const __half2*)&bp.y);
        float4 v;
        v.x = a0.x + b0.x; v.y = a0.y + b0.y; v.z = a1.x + b1.x; v.w = a1.y + b1.y;
        vv[k] = v;
        s  += v.x + v.y + v.z + v.w;
        sq += v.x * v.x + v.y * v.y + v.z * v.z + v.w * v.w;
    }
#pragma unroll
    for (int o = 16; o > 0; o >>= 1) {
        s  += __shfl_xor_sync(0xffffffffu, s, o);
        sq += __shfl_xor_sync(0xffffffffu, sq, o);
    }
    const float mean = s * (1.f / E_DIM);
    const float var  = sq * (1.f / E_DIM) - mean * mean;
    const float rstd = rsqrtf(var + 1e-5f);

#pragma unroll
    for (int k = 0; k < 8; k++) {
        const int col = k * 128 + lane * 4;
        const float4 gg = *(const float4*)(g + col);
        const float4 bb = *(const float4*)(be + col);
        float4 o4;
        o4.x = (vv[k].x - mean) * rstd * gg.x + bb.x;
        o4.y = (vv[k].y - mean) * rstd * gg.y + bb.y;
        o4.z = (vv[k].z - mean) * rstd * gg.z + bb.z;
        o4.w = (vv[k].w - mean) * rstd * gg.w + bb.w;
        __half2 h0 = __floats2half2_rn(o4.x, o4.y);
        __half2 h1 = __floats2half2_rn(o4.z, o4.w);
        uint2 pk;
        pk.x = *(uint32_t*)&h0;
        pk.y = *(uint32_t*)&h1;
        *(uint2*)(out_h + (size_t)row * E_DIM + col) = pk;
    }
}

// ---------------------------------------------------------------------------
// LN2: out = LayerNorm(X1 + P0 + P1 + b2) * g + be   (split-K FFN2 reduce)
// X1, P0, P1 fp16; b2, g, be fp32; out fp32. Warp-per-row.
// ---------------------------------------------------------------------------
__global__ __launch_bounds__(256)
void add_ln2(const __half* __restrict__ X1, const __half* __restrict__ P0,
             const __half* __restrict__ P1, const float* __restrict__ b2,
             const float* __restrict__ g, const float* __restrict__ be,
             float* __restrict__ out)
{
    const int warp = threadIdx.x >> 5;
    const int lane = threadIdx.x & 31;
    const int row = blockIdx.x * 8 + warp;

    const __half* Xr = X1 + (size_t)row * E_DIM;
    const __half* P0r = P0 + (size_t)row * E_DIM;
    const __half* P1r = P1 + (size_t)row * E_DIM;

    float4 vv[8];
    float s = 0.f, sq = 0.f;
#pragma unroll
    for (int k = 0; k < 8; k++) {
        const int col = k * 128 + lane * 4;
        const uint2 xp = *(const uint2*)(Xr + col);
        const uint2 p0 = *(const uint2*)(P0r + col);
        const uint2 p1 = *(const uint2*)(P1r + col);
        const float4 bz = *(const float4*)(b2 + col);
        const float2 x0 = __half22float2(*(const __half2*)&xp.x);
        const float2 x1 = __half22float2(*(const __half2*)&xp.y);
        const float2 a0 = __half22float2(*(const __half2*)&p0.x);
        const float2 a1 = __half22float2(*(const __half2*)&p0.y);
        const float2 c0 = __half22float2(*(const __half2*)&p1.x);
        const float2 c1 = __half22float2(*(const __half2*)&p1.y);
        float4 v;
        v.x = x0.x + a0.x + c0.x + bz.x;
        v.y = x0.y + a0.y + c0.y + bz.y;
        v.z = x1.x + a1.x + c1.x + bz.z;
        v.w = x1.y + a1.y + c1.y + bz.w;
        vv[k] = v;
        s  += v.x + v.y + v.z + v.w;
        sq += v.x * v.x + v.y * v.y + v.z * v.z + v.w * v.w;
    }
#pragma unroll
    for (int o = 16; o > 0; o >>= 1) {
        s  += __shfl_xor_sync(0xffffffffu, s, o);
        sq += __shfl_xor_sync(0xffffffffu, sq, o);
    }
    const float mean = s * (1.f / E_DIM);
    const float var  = sq * (1.f / E_DIM) - mean * mean;
    const float rstd = rsqrtf(var + 1e-5f);

#pragma unroll
    for (int k = 0; k < 8; k++) {
        const int col = k * 128 + lane * 4;
        const float4 gg = *(const float4*)(g + col);
        const float4 bb = *(const float4*)(be + col);
        float4 o4;
        o4.x = (vv[k].x - mean) * rstd * gg.x + bb.x;
        o4.y = (vv[k].y - mean) * rstd * gg.y + bb.y;
        o4.z = (vv[k].z - mean) * rstd * gg.z + bb.z;
        o4.w = (vv[k].w - mean) * rstd * gg.w + bb.w;
        *(float4*)(out + (size_t)row * E_DIM + col) = o4;
    }
}

// ---------------------------------------------------------------------------
extern "C" void kernel_launch(void* const* d_in, const int* in_sizes, int n_in,
                              void* d_out, int out_size)
{
    const float* x   = (const float*)d_in[0];
    const float* Wq  = (const float*)d_in[1];
    const float* bq  = (const float*)d_in[2];
    const float* Wk  = (const float*)d_in[3];
    const float* bk  = (const float*)d_in[4];
    const float* Wv  = (const float*)d_in[5];
    const float* bv  = (const float*)d_in[6];
    const float* g1  = (const float*)d_in[7];
    const float* be1 = (const float*)d_in[8];
    const float* W1  = (const float*)d_in[9];
    const float* b1  = (const float*)d_in[10];
    const float* W2  = (const float*)d_in[11];
    const float* b2  = (const float*)d_in[12];
    const float* g2  = (const float*)d_in[13];
    const float* be2 = (const float*)d_in[14];
    float* out = (float*)d_out;

    const int M = in_sizes[0] / E_DIM;   // 16384

    __half *ATh, *F0, *F1, *Qh, *Kh, *Vh, *xh, *X1h, *Hh, *Wqh, *Wkh, *Wvh, *W1h, *W2h;
    cudaGetSymbolAddress((void**)&ATh, g_ATh);
    cudaGetSymbolAddress((void**)&F0,  g_F0);
    cudaGetSymbolAddress((void**)&F1,  g_F1);
    cudaGetSymbolAddress((void**)&Qh,  g_Qh);
    cudaGetSymbolAddress((void**)&Kh,  g_Kh);
    cudaGetSymbolAddress((void**)&Vh,  g_Vh);
    cudaGetSymbolAddress((void**)&xh,  g_xh);
    cudaGetSymbolAddress((void**)&X1h, g_X1h);
    cudaGetSymbolAddress((void**)&Hh,  g_Hh);
    cudaGetSymbolAddress((void**)&Wqh, g_Wqh);
    cudaGetSymbolAddress((void**)&Wkh, g_Wkh);
    cudaGetSymbolAddress((void**)&Wvh, g_Wvh);
    cudaGetSymbolAddress((void**)&W1h, g_W1h);
    cudaGetSymbolAddress((void**)&W2h, g_W2h);

    cudaFuncSetAttribute(gemm_fp16<0,1,1>, cudaFuncAttributeMaxDynamicSharedMemorySize, GEMM_SMEM_BYTES);
    cudaFuncSetAttribute(gemm_fp16<1,1,1>, cudaFuncAttributeMaxDynamicSharedMemorySize, GEMM_SMEM_BYTES);
    cudaFuncSetAttribute(gemm_fp16<0,1,0>, cudaFuncAttributeMaxDynamicSharedMemorySize, GEMM_SMEM_BYTES);
    cudaFuncSetAttribute(window_attn_mma, cudaFuncAttributeMaxDynamicSharedMemorySize, AT_SMEM);

    const dim3 blk(256);

    // --- fp16 conversion of GEMM operands ---
    {
        const size_t nx = (size_t)M * E_DIM / 4;
        to_half_kernel<<<(unsigned)((nx + 255) / 256), blk>>>(x, xh, nx);
        const size_t nw = (size_t)E_DIM * E_DIM / 4;
        to_half_kernel<<<(unsigned)((nw + 255) / 256), blk>>>(Wq, Wqh, nw);
        to_half_kernel<<<(unsigned)((nw + 255) / 256), blk>>>(Wk, Wkh, nw);
        to_half_kernel<<<(unsigned)((nw + 255) / 256), blk>>>(Wv, Wvh, nw);
        const size_t nf = (size_t)E_DIM * HID_DIM / 4;
        to_half_kernel<<<(unsigned)((nf + 255) / 256), blk>>>(W1, W1h, nf);
        to_half_kernel<<<(unsigned)((nf + 255) / 256), blk>>>(W2, W2h, nf);
    }

    // Merged QKV projection -> fp16 Q/K/V
    GemmOuts qkv;
    qkv.B[0] = Wqh; qkv.B[1] = Wkh; qkv.B[2] = Wvh;
    qkv.bias[0] = bq; qkv.bias[1] = bk; qkv.bias[2] = bv;
    qkv.C[0] = Qh; qkv.C[1] = Kh; qkv.C[2] = Vh;
    gemm_fp16<0,1,1><<<dim3(E_DIM / 128, M / 128, 3), blk, GEMM_SMEM_BYTES>>>(
        xh, qkv, M, E_DIM, E_DIM, E_DIM, 0);

    window_attn_mma<<<M / WSZ, blk, AT_SMEM>>>(Qh, Kh, Vh, ATh);

    // LN1: A = xh (fp16), B = attention out (fp16) -> X1h (fp16)
    add_ln1<<<M / 8, blk>>>(xh, ATh, g1, be1, X1h);

    // FFN1: A = fp16 X1, output H in fp16 (consumed by FFN2)
    GemmOuts f1; f1.B[0] = W1h; f1.bias[0] = b1; f1.C[0] = Hh;
    f1.B[1] = f1.B[2] = W1h; f1.bias[1] = f1.bias[2] = b1; f1.C[1] = f1.C[2] = Hh;
    gemm_fp16<1,1,1><<<dim3(HID_DIM / 128, M / 128, 1), blk, GEMM_SMEM_BYTES>>>(
        X1h, f1, M, HID_DIM, E_DIM, E_DIM, 0);

    // FFN2 split-K=2: z selects K-half; bias-free fp16 partials P0/P1
    GemmOuts f2;
    f2.B[0] = W2h;
    f2.B[1] = W2h + (size_t)(HID_DIM / 2) * E_DIM;
    f2.B[2] = f2.B[0];
    f2.bias[0] = f2.bias[1] = f2.bias[2] = b2;   // unused (BIAS=0)
    f2.C[0] = F0; f2.C[1] = F1; f2.C[2] = F0;
    gemm_fp16<0,1,0><<<dim3(E_DIM / 128, M / 128, 2), blk, GEMM_SMEM_BYTES>>>(
        Hh, f2, M, E_DIM, HID_DIM / 2, HID_DIM, HID_DIM / 2);

    // LN2: reduce partials + bias + residual -> fp32 out
    add_ln2<<<M / 8, blk>>>(X1h, F0, F1, b2, g2, be2, out);
}